// round 8
// baseline (speedup 1.0000x reference)
#include <cuda_runtime.h>
#include <cuda_fp16.h>
#include <math.h>
#include <stdint.h>

#define NN 100000
#define NE 3200000
#define NL 1000000
#define F_IN 512
#define H1 128
#define H2 64
#define NBLK ((NN + 1023) / 1024)

// ---------------- scratch (static device globals; no allocs) ----------------
__device__ __half g_h1lin_s[(size_t)NN * H1];   // fp16 dinv-scaled pre-agg layer1
__device__ __half g_h1_h  [(size_t)NN * H1];    // fp16 post-relu layer1
__device__ __half g_h2lin_s[(size_t)NN * H2];   // fp16 dinv-scaled pre-agg layer2
__device__ __half g_h2_h  [(size_t)NN * H2];    // fp16 post-relu layer2
__device__ float  g_dinv [NN];
__device__ int    g_count[NN];
__device__ int    g_rowptr[NN + 1];
__device__ int    g_cursor[NN];
__device__ int    g_csr  [NE];
__device__ int    g_bsum [NBLK];
__device__ int    g_bpre [NBLK];
__device__ __half g_w1h[(size_t)H1 * F_IN];     // W1^T hi [128][512]
__device__ __half g_w1l[(size_t)H1 * F_IN];     // W1^T lo
__device__ __half g_w2h[(size_t)H2 * H1];       // W2^T hi [64][128]
__device__ __half g_w2l[(size_t)H2 * H1];       // W2^T lo
__device__ __half g_fw1h[(size_t)64 * 64];      // fcW1^T hi [64n][64k]
__device__ __half g_fw1l[(size_t)64 * 64];      // fcW1^T lo

// ---------------- helpers ----------------
__device__ __forceinline__ uint32_t smem_u32(const void* p) {
    uint32_t a;
    asm("{ .reg .u64 t; cvta.to.shared.u64 t, %1; cvt.u32.u64 %0, t; }" : "=r"(a) : "l"(p));
    return a;
}
#define HMMA(c, a, b) \
    asm volatile("mma.sync.aligned.m16n8k16.row.col.f32.f16.f16.f32 " \
                 "{%0,%1,%2,%3}, {%4,%5,%6,%7}, {%8,%9}, {%0,%1,%2,%3};" \
                 : "+f"((c)[0]), "+f"((c)[1]), "+f"((c)[2]), "+f"((c)[3]) \
                 : "r"((a)[0]), "r"((a)[1]), "r"((a)[2]), "r"((a)[3]), \
                   "r"((b)[0]), "r"((b)[1]))

__device__ __forceinline__ void ldsm_x4(uint32_t* r, uint32_t addr) {
    asm volatile("ldmatrix.sync.aligned.m8n8.x4.shared.b16 {%0,%1,%2,%3}, [%4];"
                 : "=r"(r[0]), "=r"(r[1]), "=r"(r[2]), "=r"(r[3]) : "r"(addr));
}

__device__ __forceinline__ void acc8_add(float* acc, uint4 v) {
    const uint32_t* p = (const uint32_t*)&v;
    #pragma unroll
    for (int q = 0; q < 4; q++) {
        float2 f = __half22float2(*(__half2*)&p[q]);
        acc[q * 2] += f.x;
        acc[q * 2 + 1] += f.y;
    }
}

// ---------------- CSR build ----------------
__global__ void k_zero_count() {
    int i = blockIdx.x * blockDim.x + threadIdx.x;
    if (i < NN) g_count[i] = 0;
}
__global__ void k_hist(const int* __restrict__ dst) {
    int i = blockIdx.x * blockDim.x + threadIdx.x;
    if (i < NE) atomicAdd(&g_count[dst[i]], 1);
}
__global__ void k_dinv() {
    int i = blockIdx.x * blockDim.x + threadIdx.x;
    if (i < NN) g_dinv[i] = rsqrtf((float)(g_count[i] + 1));
}
__global__ void k_bsum() {
    __shared__ int ws[32];
    int t = threadIdx.x, lane = t & 31, wid = t >> 5;
    int i = blockIdx.x * 1024 + t;
    int v = (i < NN) ? g_count[i] : 0;
    #pragma unroll
    for (int o = 16; o; o >>= 1) v += __shfl_down_sync(0xffffffffu, v, o);
    if (lane == 0) ws[wid] = v;
    __syncthreads();
    if (wid == 0) {
        int x = ws[lane];
        #pragma unroll
        for (int o = 16; o; o >>= 1) x += __shfl_down_sync(0xffffffffu, x, o);
        if (lane == 0) g_bsum[blockIdx.x] = x;
    }
}
__global__ void k_bscan() {
    __shared__ int ws[4];
    int t = threadIdx.x, lane = t & 31, wid = t >> 5;
    int v = (t < NBLK) ? g_bsum[t] : 0;
    int x = v;
    #pragma unroll
    for (int o = 1; o < 32; o <<= 1) {
        int y = __shfl_up_sync(0xffffffffu, x, o);
        if (lane >= o) x += y;
    }
    if (lane == 31) ws[wid] = x;
    __syncthreads();
    int add = 0;
    for (int w = 0; w < wid; w++) add += ws[w];
    int incl = x + add;
    if (t < NBLK) g_bpre[t] = incl - v;
    if (t == 127) g_rowptr[NN] = incl;
}
__global__ void k_scat() {
    __shared__ int ws[32];
    int t = threadIdx.x, lane = t & 31, wid = t >> 5;
    int i = blockIdx.x * 1024 + t;
    int v = (i < NN) ? g_count[i] : 0;
    int x = v;
    #pragma unroll
    for (int o = 1; o < 32; o <<= 1) {
        int y = __shfl_up_sync(0xffffffffu, x, o);
        if (lane >= o) x += y;
    }
    if (lane == 31) ws[wid] = x;
    __syncthreads();
    if (wid == 0) {
        int w = ws[lane];
        #pragma unroll
        for (int o = 1; o < 32; o <<= 1) {
            int y = __shfl_up_sync(0xffffffffu, w, o);
            if (lane >= o) w += y;
        }
        ws[lane] = w;
    }
    __syncthreads();
    int excl = g_bpre[blockIdx.x] + (wid ? ws[wid - 1] : 0) + x - v;
    if (i < NN) { g_rowptr[i] = excl; g_cursor[i] = excl; }
}
__global__ void k_fill(const int* __restrict__ src, const int* __restrict__ dst) {
    int i = blockIdx.x * blockDim.x + threadIdx.x;
    if (i < NE) {
        int p = atomicAdd(&g_cursor[dst[i]], 1);
        g_csr[p] = src[i];
    }
}

// ---------------- weight transposes + fp16 hi/lo splits ----------------
__global__ void k_wsplit(const float* __restrict__ W1) {
    int i = blockIdx.x * blockDim.x + threadIdx.x;
    if (i < H1 * F_IN) {
        int n = i & (H1 - 1);
        int k = i >> 7;
        float w = W1[(size_t)k * H1 + n];
        __half h = __float2half_rn(w);
        g_w1h[(size_t)n * F_IN + k] = h;
        g_w1l[(size_t)n * F_IN + k] = __float2half_rn(w - __half2float(h));
    }
}
__global__ void k_wsplit2(const float* __restrict__ W2) {
    int i = blockIdx.x * blockDim.x + threadIdx.x;
    if (i < H2 * H1) {
        int n = i & (H2 - 1);
        int k = i >> 6;
        float w = W2[(size_t)k * H2 + n];
        __half h = __float2half_rn(w);
        g_w2h[(size_t)n * H1 + k] = h;
        g_w2l[(size_t)n * H1 + k] = __float2half_rn(w - __half2float(h));
    }
}
__global__ void k_wsplitFC(const float* __restrict__ fcW1) {
    int i = blockIdx.x * blockDim.x + threadIdx.x;
    if (i < 64 * 64) {
        int n = i & 63;
        int k = i >> 6;
        float w = fcW1[(size_t)k * 64 + n];
        __half h = __float2half_rn(w);
        g_fw1h[(size_t)n * 64 + k] = h;
        g_fw1l[(size_t)n * 64 + k] = __float2half_rn(w - __half2float(h));
    }
}

// ---------------- GEMM1 fp16x3 HMMA: h1lin_s = dinv * (x @ W1) ----------------
#define G1_STAGE_H 20480
#define G1_SMEM (2 * G1_STAGE_H * 2)

__global__ void __launch_bounds__(256, 1)
k_gemm1_mma(const float* __restrict__ A) {
    extern __shared__ __half smh[];
    const int tid = threadIdx.x, lane = tid & 31, wid = tid >> 5;
    const int gid = lane >> 2, tq = lane & 3;
    const int rowBase = blockIdx.x * 128;
    const int wm = (wid >> 1) * 32, wn = (wid & 1) * 64;
    // ldmatrix lane geometry
    const int lt = lane >> 3, lr = lane & 7;
    const int arow = (lt & 1) * 8 + lr, acol = (lt >> 1) * 8;   // A tiles
    const int bn = (lt >> 1) * 8 + lr, bk = (lt & 1) * 8;       // B tiles

    float acc[2][8][4];
    #pragma unroll
    for (int mt = 0; mt < 2; mt++)
        #pragma unroll
        for (int nt = 0; nt < 8; nt++)
            #pragma unroll
            for (int i = 0; i < 4; i++) acc[mt][nt][i] = 0.f;

    float4 pa[4];
    auto ldgA = [&](int kt) {
        #pragma unroll
        for (int l = 0; l < 4; l++) {
            int f = tid + l * 256;
            int row = f >> 3, c4 = f & 7;
            int gr = rowBase + row;
            pa[l] = (gr < NN) ? *(const float4*)&A[(size_t)gr * F_IN + kt + c4 * 4]
                              : make_float4(0.f, 0.f, 0.f, 0.f);
        }
    };
    auto stsA = [&](__half* buf) {
        #pragma unroll
        for (int l = 0; l < 4; l++) {
            int f = tid + l * 256;
            int row = f >> 3, c4 = f & 7;
            float4 v = pa[l];
            __half hx = __float2half_rn(v.x), hy = __float2half_rn(v.y);
            __half hz = __float2half_rn(v.z), hw = __float2half_rn(v.w);
            __half lx = __float2half_rn(v.x - __half2float(hx));
            __half ly = __float2half_rn(v.y - __half2float(hy));
            __half lz = __float2half_rn(v.z - __half2float(hz));
            __half lw = __float2half_rn(v.w - __half2float(hw));
            __half2 h0 = __halves2half2(hx, hy), h1v = __halves2half2(hz, hw);
            __half2 l0 = __halves2half2(lx, ly), l1v = __halves2half2(lz, lw);
            *(uint2*)&buf[row * 40 + c4 * 4] =
                make_uint2(*(uint32_t*)&h0, *(uint32_t*)&h1v);
            *(uint2*)&buf[5120 + row * 40 + c4 * 4] =
                make_uint2(*(uint32_t*)&l0, *(uint32_t*)&l1v);
        }
    };
    auto cpB = [&](int kt, __half* buf) {
        #pragma unroll
        for (int l = 0; l < 4; l++) {
            int idx = tid + l * 256;
            int sel = idx >> 9;
            int j = idx & 511;
            int r = j >> 2, c8 = j & 3;
            const __half* g = (sel ? g_w1l : g_w1h) + (size_t)r * F_IN + kt + c8 * 8;
            __half* s = buf + 10240 + sel * 5120 + r * 40 + c8 * 8;
            uint32_t sa = smem_u32(s);
            asm volatile("cp.async.cg.shared.global [%0], [%1], 16;\n" :: "r"(sa), "l"(g));
        }
        asm volatile("cp.async.commit_group;\n");
    };

    ldgA(0);
    cpB(0, smh);
    stsA(smh);
    asm volatile("cp.async.wait_group 0;\n");
    __syncthreads();

    for (int s = 0; s < 16; s++) {
        __half* cur = smh + (s & 1) * G1_STAGE_H;
        __half* nxt = smh + ((s + 1) & 1) * G1_STAGE_H;
        if (s + 1 < 16) { cpB((s + 1) * 32, nxt); ldgA((s + 1) * 32); }

        const __half* Ah = cur;
        const __half* Al = cur + 5120;
        const __half* Bh = cur + 10240;
        const __half* Bl = cur + 15360;

        #pragma unroll
        for (int ks = 0; ks < 2; ks++) {
            int kb = ks * 16;
            uint32_t ah[2][4], al[2][4];
            #pragma unroll
            for (int mt = 0; mt < 2; mt++) {
                ldsm_x4(ah[mt], smem_u32(&Ah[(wm + mt * 16 + arow) * 40 + kb + acol]));
                ldsm_x4(al[mt], smem_u32(&Al[(wm + mt * 16 + arow) * 40 + kb + acol]));
            }
            uint32_t bh[8][2], bl[8][2];
            #pragma unroll
            for (int g2 = 0; g2 < 4; g2++) {
                uint32_t tb[4];
                ldsm_x4(tb, smem_u32(&Bh[(wn + g2 * 16 + bn) * 40 + kb + bk]));
                bh[g2 * 2][0] = tb[0]; bh[g2 * 2][1] = tb[1];
                bh[g2 * 2 + 1][0] = tb[2]; bh[g2 * 2 + 1][1] = tb[3];
                ldsm_x4(tb, smem_u32(&Bl[(wn + g2 * 16 + bn) * 40 + kb + bk]));
                bl[g2 * 2][0] = tb[0]; bl[g2 * 2][1] = tb[1];
                bl[g2 * 2 + 1][0] = tb[2]; bl[g2 * 2 + 1][1] = tb[3];
            }
            #pragma unroll
            for (int mt = 0; mt < 2; mt++)
                #pragma unroll
                for (int nt = 0; nt < 8; nt++) {
                    HMMA(acc[mt][nt], ah[mt], bh[nt]);
                    HMMA(acc[mt][nt], al[mt], bh[nt]);
                    HMMA(acc[mt][nt], ah[mt], bl[nt]);
                }
        }
        if (s + 1 < 16) { stsA(nxt); asm volatile("cp.async.wait_group 0;\n"); }
        __syncthreads();
    }

    #pragma unroll
    for (int mt = 0; mt < 2; mt++) {
        int row = rowBase + wm + mt * 16 + gid;
        float dv0 = (row < NN) ? g_dinv[row] : 0.f;
        float dv1 = (row + 8 < NN) ? g_dinv[row + 8] : 0.f;
        #pragma unroll
        for (int nt = 0; nt < 8; nt++) {
            int col = wn + nt * 8 + tq * 2;
            if (row < NN)
                *(__half2*)&g_h1lin_s[(size_t)row * H1 + col] =
                    __floats2half2_rn(acc[mt][nt][0] * dv0, acc[mt][nt][1] * dv0);
            if (row + 8 < NN)
                *(__half2*)&g_h1lin_s[(size_t)(row + 8) * H1 + col] =
                    __floats2half2_rn(acc[mt][nt][2] * dv1, acc[mt][nt][3] * dv1);
        }
    }
}

// ---------------- GEMM2 fp16x2 HMMA: h2lin_s = dinv * (h1 @ W2) ----------------
#define G2_STAGE_H 10240
#define G2_SMEM (2 * G2_STAGE_H * 2)

__global__ void __launch_bounds__(256, 1)
k_gemm2_mma() {
    extern __shared__ __half smh[];
    const int tid = threadIdx.x, lane = tid & 31, wid = tid >> 5;
    const int gid = lane >> 2, tq = lane & 3;
    const int rowBase = blockIdx.x * 128;
    const int wm = wid * 16;
    const int lt = lane >> 3, lr = lane & 7;
    const int arow = (lt & 1) * 8 + lr, acol = (lt >> 1) * 8;
    const int bn = (lt >> 1) * 8 + lr, bk = (lt & 1) * 8;

    float acc[8][4];
    #pragma unroll
    for (int nt = 0; nt < 8; nt++)
        #pragma unroll
        for (int i = 0; i < 4; i++) acc[nt][i] = 0.f;

    auto cpStage = [&](int kt, __half* buf) {
        #pragma unroll
        for (int l = 0; l < 2; l++) {
            int idx = tid + l * 256;
            int r = idx >> 2, c8 = idx & 3;
            int gr = rowBase + r;
            if (gr >= NN) gr = NN - 1;
            const __half* g = g_h1_h + (size_t)gr * H1 + kt + c8 * 8;
            uint32_t sa = smem_u32(buf + r * 40 + c8 * 8);
            asm volatile("cp.async.cg.shared.global [%0], [%1], 16;\n" :: "r"(sa), "l"(g));
        }
        #pragma unroll
        for (int l = 0; l < 2; l++) {
            int idx = tid + l * 256;
            int sel = idx >> 8;
            int j = idx & 255;
            int r = j >> 2, c8 = j & 3;
            const __half* g = (sel ? g_w2l : g_w2h) + (size_t)r * H1 + kt + c8 * 8;
            uint32_t sa = smem_u32(buf + 5120 + sel * 2560 + r * 40 + c8 * 8);
            asm volatile("cp.async.cg.shared.global [%0], [%1], 16;\n" :: "r"(sa), "l"(g));
        }
        asm volatile("cp.async.commit_group;\n");
    };

    cpStage(0, smh);
    asm volatile("cp.async.wait_group 0;\n");
    __syncthreads();

    for (int s = 0; s < 4; s++) {
        __half* cur = smh + (s & 1) * G2_STAGE_H;
        __half* nxt = smh + ((s + 1) & 1) * G2_STAGE_H;
        if (s + 1 < 4) cpStage((s + 1) * 32, nxt);

        const __half* Ah = cur;
        const __half* Bh = cur + 5120;
        const __half* Bl = cur + 7680;

        #pragma unroll
        for (int ks = 0; ks < 2; ks++) {
            int kb = ks * 16;
            uint32_t a[4];
            ldsm_x4(a, smem_u32(&Ah[(wm + arow) * 40 + kb + acol]));
            uint32_t bh[8][2], bl[8][2];
            #pragma unroll
            for (int g2 = 0; g2 < 4; g2++) {
                uint32_t tb[4];
                ldsm_x4(tb, smem_u32(&Bh[(g2 * 16 + bn) * 40 + kb + bk]));
                bh[g2 * 2][0] = tb[0]; bh[g2 * 2][1] = tb[1];
                bh[g2 * 2 + 1][0] = tb[2]; bh[g2 * 2 + 1][1] = tb[3];
                ldsm_x4(tb, smem_u32(&Bl[(g2 * 16 + bn) * 40 + kb + bk]));
                bl[g2 * 2][0] = tb[0]; bl[g2 * 2][1] = tb[1];
                bl[g2 * 2 + 1][0] = tb[2]; bl[g2 * 2 + 1][1] = tb[3];
            }
            #pragma unroll
            for (int nt = 0; nt < 8; nt++) {
                HMMA(acc[nt], a, bh[nt]);
                HMMA(acc[nt], a, bl[nt]);
            }
        }
        if (s + 1 < 4) asm volatile("cp.async.wait_group 0;\n");
        __syncthreads();
    }

    int row = rowBase + wm + gid;
    float dv0 = (row < NN) ? g_dinv[row] : 0.f;
    float dv1 = (row + 8 < NN) ? g_dinv[row + 8] : 0.f;
    #pragma unroll
    for (int nt = 0; nt < 8; nt++) {
        int col = nt * 8 + tq * 2;
        if (row < NN)
            *(__half2*)&g_h2lin_s[(size_t)row * H2 + col] =
                __floats2half2_rn(acc[nt][0] * dv0, acc[nt][1] * dv0);
        if (row + 8 < NN)
            *(__half2*)&g_h2lin_s[(size_t)(row + 8) * H2 + col] =
                __floats2half2_rn(acc[nt][2] * dv1, acc[nt][3] * dv1);
    }
}

// ---------------- aggregation: pure row-sum of pre-scaled fp16 rows ----------------
__global__ void k_agg128(const float* __restrict__ bias) {
    int gw = (blockIdx.x * blockDim.x + threadIdx.x) >> 5;
    int lane = threadIdx.x & 31;
    if (gw >= NN) return;
    int half = lane >> 4, fl = lane & 15;
    const uint4* H = (const uint4*)g_h1lin_s;
    float acc[8];
    #pragma unroll
    for (int i = 0; i < 8; i++) acc[i] = 0.f;
    if (half == 0) acc8_add(acc, H[(size_t)gw * 16 + fl]);
    int s0 = g_rowptr[gw], s1 = g_rowptr[gw + 1];
    for (int base = s0; base < s1; base += 32) {
        int rem = s1 - base;
        int cnt = rem < 32 ? rem : 32;
        int s = (lane < rem) ? g_csr[base + lane] : 0;
        for (int jj = 0; jj < cnt; jj += 2) {
            int j = jj + half;
            int ss = __shfl_sync(0xffffffffu, s, j < cnt ? j : 0);
            if (j < cnt) acc8_add(acc, H[(size_t)ss * 16 + fl]);
        }
    }
    #pragma unroll
    for (int i = 0; i < 8; i++) acc[i] += __shfl_xor_sync(0xffffffffu, acc[i], 16);
    if (half == 0) {
        float dd = g_dinv[gw];
        float4 b0 = *(const float4*)&bias[fl * 8];
        float4 b1 = *(const float4*)&bias[fl * 8 + 4];
        __half2 o[4];
        o[0] = __floats2half2_rn(fmaxf(acc[0] * dd + b0.x, 0.f), fmaxf(acc[1] * dd + b0.y, 0.f));
        o[1] = __floats2half2_rn(fmaxf(acc[2] * dd + b0.z, 0.f), fmaxf(acc[3] * dd + b0.w, 0.f));
        o[2] = __floats2half2_rn(fmaxf(acc[4] * dd + b1.x, 0.f), fmaxf(acc[5] * dd + b1.y, 0.f));
        o[3] = __floats2half2_rn(fmaxf(acc[6] * dd + b1.z, 0.f), fmaxf(acc[7] * dd + b1.w, 0.f));
        ((uint4*)g_h1_h)[(size_t)gw * 16 + fl] =
            make_uint4(*(uint32_t*)&o[0], *(uint32_t*)&o[1], *(uint32_t*)&o[2], *(uint32_t*)&o[3]);
    }
}

__global__ void k_agg64(const float* __restrict__ bias) {
    int gw = (blockIdx.x * blockDim.x + threadIdx.x) >> 5;
    int lane = threadIdx.x & 31;
    if (gw >= NN) return;
    int q4 = lane >> 3, fl = lane & 7;
    const uint4* H = (const uint4*)g_h2lin_s;
    float acc[8];
    #pragma unroll
    for (int i = 0; i < 8; i++) acc[i] = 0.f;
    if (q4 == 0) acc8_add(acc, H[(size_t)gw * 8 + fl]);
    int s0 = g_rowptr[gw], s1 = g_rowptr[gw + 1];
    for (int base = s0; base < s1; base += 32) {
        int rem = s1 - base;
        int cnt = rem < 32 ? rem : 32;
        int s = (lane < rem) ? g_csr[base + lane] : 0;
        for (int jj = 0; jj < cnt; jj += 4) {
            int j = jj + q4;
            int ss = __shfl_sync(0xffffffffu, s, j < cnt ? j : 0);
            if (j < cnt) acc8_add(acc, H[(size_t)ss * 8 + fl]);
        }
    }
    #pragma unroll
    for (int i = 0; i < 8; i++) {
        acc[i] += __shfl_xor_sync(0xffffffffu, acc[i], 8);
        acc[i] += __shfl_xor_sync(0xffffffffu, acc[i], 16);
    }
    if (lane < 8) {
        float dd = g_dinv[gw];
        float4 b0 = *(const float4*)&bias[fl * 8];
        float4 b1 = *(const float4*)&bias[fl * 8 + 4];
        __half2 o[4];
        o[0] = __floats2half2_rn(fmaxf(acc[0] * dd + b0.x, 0.f), fmaxf(acc[1] * dd + b0.y, 0.f));
        o[1] = __floats2half2_rn(fmaxf(acc[2] * dd + b0.z, 0.f), fmaxf(acc[3] * dd + b0.w, 0.f));
        o[2] = __floats2half2_rn(fmaxf(acc[4] * dd + b1.x, 0.f), fmaxf(acc[5] * dd + b1.y, 0.f));
        o[3] = __floats2half2_rn(fmaxf(acc[6] * dd + b1.z, 0.f), fmaxf(acc[7] * dd + b1.w, 0.f));
        ((uint4*)g_h2_h)[(size_t)gw * 8 + fl] =
            make_uint4(*(uint32_t*)&o[0], *(uint32_t*)&o[1], *(uint32_t*)&o[2], *(uint32_t*)&o[3]);
    }
}

// ---------------- edge scorer fp16 HMMA ----------------
#define SC_SMEM 56064

__global__ void __launch_bounds__(256, 1)
k_score_mma(const int* __restrict__ la, const int* __restrict__ lb,
            const float* __restrict__ fcb1,
            const float* __restrict__ fcW2, const float* __restrict__ fcb2,
            float* __restrict__ out) {
    extern __shared__ __half smh[];
    __half* Th = smh;
    __half* Tl = smh + 9216;
    __half* Wh = smh + 18432;
    __half* Wl = smh + 23040;
    float* w2s = (float*)((char*)smh + 55296);
    float* b1s = (float*)((char*)smh + 55808);
    const int tid = threadIdx.x, lane = tid & 31, wid = tid >> 5;
    const int gid = lane >> 2, tq = lane & 3;
    const int e0 = blockIdx.x * 128;
    const int lt = lane >> 3, lr = lane & 7;
    const int arow = (lt & 1) * 8 + lr, acol = (lt >> 1) * 8;
    const int bn = (lt >> 1) * 8 + lr, bk = (lt & 1) * 8;

    #pragma unroll
    for (int l = 0; l < 4; l++) {
        int idx = tid + l * 256;
        int sel = idx >> 9;
        int j = idx & 511;
        int n = j >> 3, c8 = j & 7;
        const __half* g = (sel ? g_fw1l : g_fw1h) + (size_t)n * 64 + c8 * 8;
        __half* s = (sel ? Wl : Wh) + n * 72 + c8 * 8;
        uint32_t sa = smem_u32(s);
        asm volatile("cp.async.cg.shared.global [%0], [%1], 16;\n" :: "r"(sa), "l"(g));
    }
    asm volatile("cp.async.commit_group;\n");
    if (tid < 128) w2s[tid] = fcW2[tid];
    if (tid < 64)  b1s[tid] = fcb1[tid];

    #pragma unroll
    for (int l = 0; l < 4; l++) {
        int idx = tid + l * 256;
        int e = idx >> 3, c8 = idx & 7;
        int eg = e0 + e;
        if (eg >= NL) eg = NL - 1;
        int a = la[eg], b = lb[eg];
        uint4 va = *(const uint4*)&g_h2_h[(size_t)a * H2 + c8 * 8];
        uint4 vb = *(const uint4*)&g_h2_h[(size_t)b * H2 + c8 * 8];
        uint32_t th[4], tl[4];
        const uint32_t* pa = (const uint32_t*)&va;
        const uint32_t* pb = (const uint32_t*)&vb;
        #pragma unroll
        for (int q = 0; q < 4; q++) {
            float2 fa = __half22float2(*(__half2*)&pa[q]);
            float2 fb = __half22float2(*(__half2*)&pb[q]);
            float px = fa.x * fb.x, py = fa.y * fb.y;
            __half hx = __float2half_rn(px), hy = __float2half_rn(py);
            __half lx = __float2half_rn(px - __half2float(hx));
            __half ly = __float2half_rn(py - __half2float(hy));
            __half2 hh = __halves2half2(hx, hy), ll = __halves2half2(lx, ly);
            th[q] = *(uint32_t*)&hh;
            tl[q] = *(uint32_t*)&ll;
        }
        *(uint4*)&Th[e * 72 + c8 * 8] = make_uint4(th[0], th[1], th[2], th[3]);
        *(uint4*)&Tl[e * 72 + c8 * 8] = make_uint4(tl[0], tl[1], tl[2], tl[3]);
    }
    asm volatile("cp.async.wait_group 0;\n");
    __syncthreads();

    float acc[8][4];
    #pragma unroll
    for (int nt = 0; nt < 8; nt++)
        #pragma unroll
        for (int i = 0; i < 4; i++) acc[nt][i] = 0.f;

    const int rowT = wid * 16;
    #pragma unroll
    for (int ks = 0; ks < 4; ks++) {
        int kb = ks * 16;
        uint32_t ah[4], al[4];
        ldsm_x4(ah, smem_u32(&Th[(rowT + arow) * 72 + kb + acol]));
        ldsm_x4(al, smem_u32(&Tl[(rowT + arow) * 72 + kb + acol]));
        uint32_t bh[8][2], bl[8][2];
        #pragma unroll
        for (int g2 = 0; g2 < 4; g2++) {
            uint32_t tb[4];
            ldsm_x4(tb, smem_u32(&Wh[(g2 * 16 + bn) * 72 + kb + bk]));
            bh[g2 * 2][0] = tb[0]; bh[g2 * 2][1] = tb[1];
            bh[g2 * 2 + 1][0] = tb[2]; bh[g2 * 2 + 1][1] = tb[3];
            ldsm_x4(tb, smem_u32(&Wl[(g2 * 16 + bn) * 72 + kb + bk]));
            bl[g2 * 2][0] = tb[0]; bl[g2 * 2][1] = tb[1];
            bl[g2 * 2 + 1][0] = tb[2]; bl[g2 * 2 + 1][1] = tb[3];
        }
        #pragma unroll
        for (int nt = 0; nt < 8; nt++) {
            HMMA(acc[nt], ah, bh[nt]);
            HMMA(acc[nt], al, bh[nt]);
            HMMA(acc[nt], ah, bl[nt]);
        }
    }

    // second tiny layer in registers
    float p00 = 0.f, p01 = 0.f, p10 = 0.f, p11 = 0.f;
    #pragma unroll
    for (int nt = 0; nt < 8; nt++) {
        int col = nt * 8 + tq * 2;
        float4 w2a = *(float4*)&w2s[col * 2];
        float b0v = b1s[col], b1v = b1s[col + 1];
        float u0 = fmaxf(acc[nt][0] + b0v, 0.f);
        float u1 = fmaxf(acc[nt][1] + b1v, 0.f);
        float u2 = fmaxf(acc[nt][2] + b0v, 0.f);
        float u3 = fmaxf(acc[nt][3] + b1v, 0.f);
        p00 += u0 * w2a.x + u1 * w2a.z;
        p01 += u0 * w2a.y + u1 * w2a.w;
        p10 += u2 * w2a.x + u3 * w2a.z;
        p11 += u2 * w2a.y + u3 * w2a.w;
    }
    #pragma unroll
    for (int off = 1; off <= 2; off <<= 1) {
        p00 += __shfl_xor_sync(0xffffffffu, p00, off);
        p01 += __shfl_xor_sync(0xffffffffu, p01, off);
        p10 += __shfl_xor_sync(0xffffffffu, p10, off);
        p11 += __shfl_xor_sync(0xffffffffu, p11, off);
    }
    if (tq == 0) {
        float c0 = fcb2[0], c1 = fcb2[1];
        int e = e0 + wid * 16 + gid;
        if (e < NL)     *(float2*)&out[(size_t)e * 2]       = make_float2(p00 + c0, p01 + c1);
        if (e + 8 < NL) *(float2*)&out[(size_t)(e + 8) * 2] = make_float2(p10 + c0, p11 + c1);
    }
}

// ---------------- launch ----------------
extern "C" void kernel_launch(void* const* d_in, const int* in_sizes, int n_in,
                              void* d_out, int out_size) {
    const float* x    = (const float*)d_in[0];
    const float* W1   = (const float*)d_in[1];
    const float* b1   = (const float*)d_in[2];
    const float* W2   = (const float*)d_in[3];
    const float* b2   = (const float*)d_in[4];
    const float* fcW1 = (const float*)d_in[5];
    const float* fcb1 = (const float*)d_in[6];
    const float* fcW2 = (const float*)d_in[7];
    const float* fcb2 = (const float*)d_in[8];
    const int* eidx = (const int*)d_in[9];
    const int* elab = (const int*)d_in[10];
    const int* src = eidx;
    const int* dst = eidx + NE;
    const int* la = elab;
    const int* lb = elab + NL;
    float* out = (float*)d_out;

    static int attr_done = 0;
    static cudaStream_t s2;
    static cudaEvent_t evA, evB;
    if (!attr_done) {
        cudaFuncSetAttribute(k_gemm1_mma, cudaFuncAttributeMaxDynamicSharedMemorySize, G1_SMEM);
        cudaFuncSetAttribute(k_gemm2_mma, cudaFuncAttributeMaxDynamicSharedMemorySize, G2_SMEM);
        cudaFuncSetAttribute(k_score_mma, cudaFuncAttributeMaxDynamicSharedMemorySize, SC_SMEM);
        cudaStreamCreateWithFlags(&s2, cudaStreamNonBlocking);
        cudaEventCreateWithFlags(&evA, cudaEventDisableTiming);
        cudaEventCreateWithFlags(&evB, cudaEventDisableTiming);
        attr_done = 1;
    }

    // serial prefix: degrees (gemm epilogues need g_dinv)
    k_zero_count<<<(NN + 255) / 256, 256>>>();
    k_hist<<<(NE + 255) / 256, 256>>>(dst);
    k_dinv<<<(NN + 255) / 256, 256>>>();

    // fork: rest of CSR build on s2, weight prep + gemm1 on default
    cudaEventRecord(evA, 0);
    cudaStreamWaitEvent(s2, evA, 0);

    k_bsum<<<NBLK, 1024, 0, s2>>>();
    k_bscan<<<1, 128, 0, s2>>>();
    k_scat<<<NBLK, 1024, 0, s2>>>();
    k_fill<<<(NE + 255) / 256, 256, 0, s2>>>(src, dst);
    cudaEventRecord(evB, s2);

    k_wsplit<<<(H1 * F_IN + 255) / 256, 256>>>(W1);
    k_wsplit2<<<(H2 * H1 + 255) / 256, 256>>>(W2);
    k_wsplitFC<<<(64 * 64 + 255) / 256, 256>>>(fcW1);
    k_gemm1_mma<<<(NN + 127) / 128, 256, G1_SMEM>>>(x);

    // join
    cudaStreamWaitEvent(0, evB, 0);

    k_agg128<<<(NN * 32 + 255) / 256, 256>>>(b1);
    k_gemm2_mma<<<(NN + 127) / 128, 256, G2_SMEM>>>();
    k_agg64<<<(NN * 32 + 255) / 256, 256>>>(b2);
    k_score_mma<<<(NL + 127) / 128, 256, SC_SMEM>>>(la, lb, fcb1, fcW2, fcb2, out);
}

// round 9
// speedup vs baseline: 1.1578x; 1.1578x over previous
#include <cuda_runtime.h>
#include <cuda_fp16.h>
#include <math.h>
#include <stdint.h>

#define NN 100000
#define NE 3200000
#define NL 1000000
#define F_IN 512
#define H1 128
#define H2 64
#define NBLK ((NN + 1023) / 1024)

// ---------------- scratch (static device globals; no allocs) ----------------
__device__ __half g_h1lin_s[(size_t)NN * H1];   // pre-agg layer1 (unscaled, then scaled in place)
__device__ __half g_h1_h  [(size_t)NN * H1];    // fp16 post-relu layer1
__device__ __half g_h2lin_s[(size_t)NN * H2];   // fp16 dinv-scaled pre-agg layer2
__device__ __half g_h2_h  [(size_t)NN * H2];    // fp16 post-relu layer2
__device__ float  g_dinv [NN];
__device__ int    g_count[NN];
__device__ int    g_rowptr[NN + 1];
__device__ int    g_cursor[NN];
__device__ int    g_csr  [NE];
__device__ int    g_bsum [NBLK];
__device__ int    g_bpre [NBLK];
__device__ __half g_w1h[(size_t)H1 * F_IN];     // W1^T fp16 [128][512]
__device__ __half g_w2h[(size_t)H2 * H1];       // W2^T fp16 [64][128]
__device__ __half g_fw1h[(size_t)64 * 64];      // fcW1^T fp16 [64n][64k]

// ---------------- helpers ----------------
__device__ __forceinline__ uint32_t smem_u32(const void* p) {
    uint32_t a;
    asm("{ .reg .u64 t; cvta.to.shared.u64 t, %1; cvt.u32.u64 %0, t; }" : "=r"(a) : "l"(p));
    return a;
}
#define HMMA(c, a, b) \
    asm volatile("mma.sync.aligned.m16n8k16.row.col.f32.f16.f16.f32 " \
                 "{%0,%1,%2,%3}, {%4,%5,%6,%7}, {%8,%9}, {%0,%1,%2,%3};" \
                 : "+f"((c)[0]), "+f"((c)[1]), "+f"((c)[2]), "+f"((c)[3]) \
                 : "r"((a)[0]), "r"((a)[1]), "r"((a)[2]), "r"((a)[3]), \
                   "r"((b)[0]), "r"((b)[1]))

__device__ __forceinline__ void ldsm_x4(uint32_t* r, uint32_t addr) {
    asm volatile("ldmatrix.sync.aligned.m8n8.x4.shared.b16 {%0,%1,%2,%3}, [%4];"
                 : "=r"(r[0]), "=r"(r[1]), "=r"(r[2]), "=r"(r[3]) : "r"(addr));
}

__device__ __forceinline__ void acc8_add(float* acc, uint4 v) {
    const uint32_t* p = (const uint32_t*)&v;
    #pragma unroll
    for (int q = 0; q < 4; q++) {
        float2 f = __half22float2(*(__half2*)&p[q]);
        acc[q * 2] += f.x;
        acc[q * 2 + 1] += f.y;
    }
}

// ---------------- CSR build ----------------
__global__ void k_zero_count() {
    int i = blockIdx.x * blockDim.x + threadIdx.x;
    if (i < NN) g_count[i] = 0;
}
__global__ void k_hist(const int* __restrict__ dst) {
    int i = blockIdx.x * blockDim.x + threadIdx.x;
    if (i < NE) atomicAdd(&g_count[dst[i]], 1);
}
__global__ void k_dinv() {
    int i = blockIdx.x * blockDim.x + threadIdx.x;
    if (i < NN) g_dinv[i] = rsqrtf((float)(g_count[i] + 1));
}
__global__ void k_bsum() {
    __shared__ int ws[32];
    int t = threadIdx.x, lane = t & 31, wid = t >> 5;
    int i = blockIdx.x * 1024 + t;
    int v = (i < NN) ? g_count[i] : 0;
    #pragma unroll
    for (int o = 16; o; o >>= 1) v += __shfl_down_sync(0xffffffffu, v, o);
    if (lane == 0) ws[wid] = v;
    __syncthreads();
    if (wid == 0) {
        int x = ws[lane];
        #pragma unroll
        for (int o = 16; o; o >>= 1) x += __shfl_down_sync(0xffffffffu, x, o);
        if (lane == 0) g_bsum[blockIdx.x] = x;
    }
}
__global__ void k_bscan() {
    __shared__ int ws[4];
    int t = threadIdx.x, lane = t & 31, wid = t >> 5;
    int v = (t < NBLK) ? g_bsum[t] : 0;
    int x = v;
    #pragma unroll
    for (int o = 1; o < 32; o <<= 1) {
        int y = __shfl_up_sync(0xffffffffu, x, o);
        if (lane >= o) x += y;
    }
    if (lane == 31) ws[wid] = x;
    __syncthreads();
    int add = 0;
    for (int w = 0; w < wid; w++) add += ws[w];
    int incl = x + add;
    if (t < NBLK) g_bpre[t] = incl - v;
    if (t == 127) g_rowptr[NN] = incl;
}
__global__ void k_scat() {
    __shared__ int ws[32];
    int t = threadIdx.x, lane = t & 31, wid = t >> 5;
    int i = blockIdx.x * 1024 + t;
    int v = (i < NN) ? g_count[i] : 0;
    int x = v;
    #pragma unroll
    for (int o = 1; o < 32; o <<= 1) {
        int y = __shfl_up_sync(0xffffffffu, x, o);
        if (lane >= o) x += y;
    }
    if (lane == 31) ws[wid] = x;
    __syncthreads();
    if (wid == 0) {
        int w = ws[lane];
        #pragma unroll
        for (int o = 1; o < 32; o <<= 1) {
            int y = __shfl_up_sync(0xffffffffu, w, o);
            if (lane >= o) w += y;
        }
        ws[lane] = w;
    }
    __syncthreads();
    int excl = g_bpre[blockIdx.x] + (wid ? ws[wid - 1] : 0) + x - v;
    if (i < NN) { g_rowptr[i] = excl; g_cursor[i] = excl; }
}
__global__ void k_fill(const int* __restrict__ src, const int* __restrict__ dst) {
    int i = blockIdx.x * blockDim.x + threadIdx.x;
    if (i < NE) {
        int p = atomicAdd(&g_cursor[dst[i]], 1);
        g_csr[p] = src[i];
    }
}

// ---------------- weight transposes (fp16 hi only) ----------------
__global__ void k_wsplit(const float* __restrict__ W1) {
    int i = blockIdx.x * blockDim.x + threadIdx.x;
    if (i < H1 * F_IN) {
        int n = i & (H1 - 1);
        int k = i >> 7;
        g_w1h[(size_t)n * F_IN + k] = __float2half_rn(W1[(size_t)k * H1 + n]);
    }
}
__global__ void k_wsplit2(const float* __restrict__ W2) {
    int i = blockIdx.x * blockDim.x + threadIdx.x;
    if (i < H2 * H1) {
        int n = i & (H2 - 1);
        int k = i >> 6;
        g_w2h[(size_t)n * H1 + k] = __float2half_rn(W2[(size_t)k * H2 + n]);
    }
}
__global__ void k_wsplitFC(const float* __restrict__ fcW1) {
    int i = blockIdx.x * blockDim.x + threadIdx.x;
    if (i < 64 * 64) {
        int n = i & 63;
        int k = i >> 6;
        g_fw1h[(size_t)n * 64 + k] = __float2half_rn(fcW1[(size_t)k * 64 + n]);
    }
}

// ---------------- GEMM1 fp16x2 HMMA: h1lin = x @ W1 (unscaled) ----------------
// stage (halves, stride 40/row): Ah@0(5120) Al@5120 Bh@10240(5120) -> 15360
#define G1_STAGE_H 15360
#define G1_SMEM (2 * G1_STAGE_H * 2)

__global__ void __launch_bounds__(256, 1)
k_gemm1_mma(const float* __restrict__ A) {
    extern __shared__ __half smh[];
    const int tid = threadIdx.x, lane = tid & 31, wid = tid >> 5;
    const int gid = lane >> 2, tq = lane & 3;
    const int rowBase = blockIdx.x * 128;
    const int wm = (wid >> 1) * 32, wn = (wid & 1) * 64;
    const int lt = lane >> 3, lr = lane & 7;
    const int arow = (lt & 1) * 8 + lr, acol = (lt >> 1) * 8;
    const int bn = (lt >> 1) * 8 + lr, bk = (lt & 1) * 8;

    float acc[2][8][4];
    #pragma unroll
    for (int mt = 0; mt < 2; mt++)
        #pragma unroll
        for (int nt = 0; nt < 8; nt++)
            #pragma unroll
            for (int i = 0; i < 4; i++) acc[mt][nt][i] = 0.f;

    float4 pa[4];
    auto ldgA = [&](int kt) {
        #pragma unroll
        for (int l = 0; l < 4; l++) {
            int f = tid + l * 256;
            int row = f >> 3, c4 = f & 7;
            int gr = rowBase + row;
            pa[l] = (gr < NN) ? *(const float4*)&A[(size_t)gr * F_IN + kt + c4 * 4]
                              : make_float4(0.f, 0.f, 0.f, 0.f);
        }
    };
    auto stsA = [&](__half* buf) {
        #pragma unroll
        for (int l = 0; l < 4; l++) {
            int f = tid + l * 256;
            int row = f >> 3, c4 = f & 7;
            float4 v = pa[l];
            __half hx = __float2half_rn(v.x), hy = __float2half_rn(v.y);
            __half hz = __float2half_rn(v.z), hw = __float2half_rn(v.w);
            __half lx = __float2half_rn(v.x - __half2float(hx));
            __half ly = __float2half_rn(v.y - __half2float(hy));
            __half lz = __float2half_rn(v.z - __half2float(hz));
            __half lw = __float2half_rn(v.w - __half2float(hw));
            __half2 h0 = __halves2half2(hx, hy), h1v = __halves2half2(hz, hw);
            __half2 l0 = __halves2half2(lx, ly), l1v = __halves2half2(lz, lw);
            *(uint2*)&buf[row * 40 + c4 * 4] =
                make_uint2(*(uint32_t*)&h0, *(uint32_t*)&h1v);
            *(uint2*)&buf[5120 + row * 40 + c4 * 4] =
                make_uint2(*(uint32_t*)&l0, *(uint32_t*)&l1v);
        }
    };
    auto cpB = [&](int kt, __half* buf) {
        #pragma unroll
        for (int l = 0; l < 2; l++) {
            int j = tid + l * 256;          // 512 chunks: 128 rows x 4
            int r = j >> 2, c8 = j & 3;
            const __half* g = g_w1h + (size_t)r * F_IN + kt + c8 * 8;
            uint32_t sa = smem_u32(buf + 10240 + r * 40 + c8 * 8);
            asm volatile("cp.async.cg.shared.global [%0], [%1], 16;\n" :: "r"(sa), "l"(g));
        }
        asm volatile("cp.async.commit_group;\n");
    };

    ldgA(0);
    cpB(0, smh);
    stsA(smh);
    asm volatile("cp.async.wait_group 0;\n");
    __syncthreads();

    for (int s = 0; s < 16; s++) {
        __half* cur = smh + (s & 1) * G1_STAGE_H;
        __half* nxt = smh + ((s + 1) & 1) * G1_STAGE_H;
        if (s + 1 < 16) { cpB((s + 1) * 32, nxt); ldgA((s + 1) * 32); }

        const __half* Ah = cur;
        const __half* Al = cur + 5120;
        const __half* Bh = cur + 10240;

        #pragma unroll
        for (int ks = 0; ks < 2; ks++) {
            int kb = ks * 16;
            uint32_t ah[2][4], al[2][4];
            #pragma unroll
            for (int mt = 0; mt < 2; mt++) {
                ldsm_x4(ah[mt], smem_u32(&Ah[(wm + mt * 16 + arow) * 40 + kb + acol]));
                ldsm_x4(al[mt], smem_u32(&Al[(wm + mt * 16 + arow) * 40 + kb + acol]));
            }
            uint32_t bh[8][2];
            #pragma unroll
            for (int g2 = 0; g2 < 4; g2++) {
                uint32_t tb[4];
                ldsm_x4(tb, smem_u32(&Bh[(wn + g2 * 16 + bn) * 40 + kb + bk]));
                bh[g2 * 2][0] = tb[0]; bh[g2 * 2][1] = tb[1];
                bh[g2 * 2 + 1][0] = tb[2]; bh[g2 * 2 + 1][1] = tb[3];
            }
            #pragma unroll
            for (int mt = 0; mt < 2; mt++)
                #pragma unroll
                for (int nt = 0; nt < 8; nt++) {
                    HMMA(acc[mt][nt], ah[mt], bh[nt]);
                    HMMA(acc[mt][nt], al[mt], bh[nt]);
                }
        }
        if (s + 1 < 16) { stsA(nxt); asm volatile("cp.async.wait_group 0;\n"); }
        __syncthreads();
    }

    #pragma unroll
    for (int mt = 0; mt < 2; mt++) {
        int row = rowBase + wm + mt * 16 + gid;
        #pragma unroll
        for (int nt = 0; nt < 8; nt++) {
            int col = wn + nt * 8 + tq * 2;
            if (row < NN)
                *(__half2*)&g_h1lin_s[(size_t)row * H1 + col] =
                    __floats2half2_rn(acc[mt][nt][0], acc[mt][nt][1]);
            if (row + 8 < NN)
                *(__half2*)&g_h1lin_s[(size_t)(row + 8) * H1 + col] =
                    __floats2half2_rn(acc[mt][nt][2], acc[mt][nt][3]);
        }
    }
}

// ---------------- scale h1lin in place by dinv[row] ----------------
__global__ void k_scale1() {
    int i = blockIdx.x * blockDim.x + threadIdx.x;   // uint4 id, NN*16 total
    if (i < NN * 16) {
        int row = i >> 4;
        float dd = g_dinv[row];
        uint4 v = ((uint4*)g_h1lin_s)[i];
        uint32_t* p = (uint32_t*)&v;
        #pragma unroll
        for (int q = 0; q < 4; q++) {
            float2 f = __half22float2(*(__half2*)&p[q]);
            __half2 o = __floats2half2_rn(f.x * dd, f.y * dd);
            p[q] = *(uint32_t*)&o;
        }
        ((uint4*)g_h1lin_s)[i] = v;
    }
}

// ---------------- GEMM2 fp16x1 HMMA: h2lin_s = dinv * (h1 @ W2h) ----------------
// stage halves: A@0(5120) Bh@5120(2560) -> 7680
#define G2_STAGE_H 7680
#define G2_SMEM (2 * G2_STAGE_H * 2)

__global__ void __launch_bounds__(256, 1)
k_gemm2_mma() {
    extern __shared__ __half smh[];
    const int tid = threadIdx.x, lane = tid & 31, wid = tid >> 5;
    const int gid = lane >> 2, tq = lane & 3;
    const int rowBase = blockIdx.x * 128;
    const int wm = wid * 16;
    const int lt = lane >> 3, lr = lane & 7;
    const int arow = (lt & 1) * 8 + lr, acol = (lt >> 1) * 8;
    const int bn = (lt >> 1) * 8 + lr, bk = (lt & 1) * 8;

    float acc[8][4];
    #pragma unroll
    for (int nt = 0; nt < 8; nt++)
        #pragma unroll
        for (int i = 0; i < 4; i++) acc[nt][i] = 0.f;

    auto cpStage = [&](int kt, __half* buf) {
        #pragma unroll
        for (int l = 0; l < 2; l++) {
            int idx = tid + l * 256;
            int r = idx >> 2, c8 = idx & 3;
            int gr = rowBase + r;
            if (gr >= NN) gr = NN - 1;
            const __half* g = g_h1_h + (size_t)gr * H1 + kt + c8 * 8;
            uint32_t sa = smem_u32(buf + r * 40 + c8 * 8);
            asm volatile("cp.async.cg.shared.global [%0], [%1], 16;\n" :: "r"(sa), "l"(g));
        }
        {
            int idx = tid;                  // 256 chunks: 64 rows x 4
            int r = idx >> 2, c8 = idx & 3;
            const __half* g = g_w2h + (size_t)r * H1 + kt + c8 * 8;
            uint32_t sa = smem_u32(buf + 5120 + r * 40 + c8 * 8);
            asm volatile("cp.async.cg.shared.global [%0], [%1], 16;\n" :: "r"(sa), "l"(g));
        }
        asm volatile("cp.async.commit_group;\n");
    };

    cpStage(0, smh);
    asm volatile("cp.async.wait_group 0;\n");
    __syncthreads();

    for (int s = 0; s < 4; s++) {
        __half* cur = smh + (s & 1) * G2_STAGE_H;
        __half* nxt = smh + ((s + 1) & 1) * G2_STAGE_H;
        if (s + 1 < 4) cpStage((s + 1) * 32, nxt);

        const __half* Ah = cur;
        const __half* Bh = cur + 5120;

        #pragma unroll
        for (int ks = 0; ks < 2; ks++) {
            int kb = ks * 16;
            uint32_t a[4];
            ldsm_x4(a, smem_u32(&Ah[(wm + arow) * 40 + kb + acol]));
            uint32_t bh[8][2];
            #pragma unroll
            for (int g2 = 0; g2 < 4; g2++) {
                uint32_t tb[4];
                ldsm_x4(tb, smem_u32(&Bh[(g2 * 16 + bn) * 40 + kb + bk]));
                bh[g2 * 2][0] = tb[0]; bh[g2 * 2][1] = tb[1];
                bh[g2 * 2 + 1][0] = tb[2]; bh[g2 * 2 + 1][1] = tb[3];
            }
            #pragma unroll
            for (int nt = 0; nt < 8; nt++)
                HMMA(acc[nt], a, bh[nt]);
        }
        if (s + 1 < 4) asm volatile("cp.async.wait_group 0;\n");
        __syncthreads();
    }

    int row = rowBase + wm + gid;
    float dv0 = (row < NN) ? g_dinv[row] : 0.f;
    float dv1 = (row + 8 < NN) ? g_dinv[row + 8] : 0.f;
    #pragma unroll
    for (int nt = 0; nt < 8; nt++) {
        int col = nt * 8 + tq * 2;
        if (row < NN)
            *(__half2*)&g_h2lin_s[(size_t)row * H2 + col] =
                __floats2half2_rn(acc[nt][0] * dv0, acc[nt][1] * dv0);
        if (row + 8 < NN)
            *(__half2*)&g_h2lin_s[(size_t)(row + 8) * H2 + col] =
                __floats2half2_rn(acc[nt][2] * dv1, acc[nt][3] * dv1);
    }
}

// ---------------- aggregation: pure row-sum of pre-scaled fp16 rows ----------------
__global__ void k_agg128(const float* __restrict__ bias) {
    int gw = (blockIdx.x * blockDim.x + threadIdx.x) >> 5;
    int lane = threadIdx.x & 31;
    if (gw >= NN) return;
    int half = lane >> 4, fl = lane & 15;
    const uint4* H = (const uint4*)g_h1lin_s;
    float acc[8];
    #pragma unroll
    for (int i = 0; i < 8; i++) acc[i] = 0.f;
    if (half == 0) acc8_add(acc, H[(size_t)gw * 16 + fl]);
    int s0 = g_rowptr[gw], s1 = g_rowptr[gw + 1];
    for (int base = s0; base < s1; base += 32) {
        int rem = s1 - base;
        int cnt = rem < 32 ? rem : 32;
        int s = (lane < rem) ? g_csr[base + lane] : 0;
        for (int jj = 0; jj < cnt; jj += 2) {
            int j = jj + half;
            int ss = __shfl_sync(0xffffffffu, s, j < cnt ? j : 0);
            if (j < cnt) acc8_add(acc, H[(size_t)ss * 16 + fl]);
        }
    }
    #pragma unroll
    for (int i = 0; i < 8; i++) acc[i] += __shfl_xor_sync(0xffffffffu, acc[i], 16);
    if (half == 0) {
        float dd = g_dinv[gw];
        float4 b0 = *(const float4*)&bias[fl * 8];
        float4 b1 = *(const float4*)&bias[fl * 8 + 4];
        __half2 o[4];
        o[0] = __floats2half2_rn(fmaxf(acc[0] * dd + b0.x, 0.f), fmaxf(acc[1] * dd + b0.y, 0.f));
        o[1] = __floats2half2_rn(fmaxf(acc[2] * dd + b0.z, 0.f), fmaxf(acc[3] * dd + b0.w, 0.f));
        o[2] = __floats2half2_rn(fmaxf(acc[4] * dd + b1.x, 0.f), fmaxf(acc[5] * dd + b1.y, 0.f));
        o[3] = __floats2half2_rn(fmaxf(acc[6] * dd + b1.z, 0.f), fmaxf(acc[7] * dd + b1.w, 0.f));
        ((uint4*)g_h1_h)[(size_t)gw * 16 + fl] =
            make_uint4(*(uint32_t*)&o[0], *(uint32_t*)&o[1], *(uint32_t*)&o[2], *(uint32_t*)&o[3]);
    }
}

__global__ void k_agg64(const float* __restrict__ bias) {
    int gw = (blockIdx.x * blockDim.x + threadIdx.x) >> 5;
    int lane = threadIdx.x & 31;
    if (gw >= NN) return;
    int q4 = lane >> 3, fl = lane & 7;
    const uint4* H = (const uint4*)g_h2lin_s;
    float acc[8];
    #pragma unroll
    for (int i = 0; i < 8; i++) acc[i] = 0.f;
    if (q4 == 0) acc8_add(acc, H[(size_t)gw * 8 + fl]);
    int s0 = g_rowptr[gw], s1 = g_rowptr[gw + 1];
    for (int base = s0; base < s1; base += 32) {
        int rem = s1 - base;
        int cnt = rem < 32 ? rem : 32;
        int s = (lane < rem) ? g_csr[base + lane] : 0;
        for (int jj = 0; jj < cnt; jj += 4) {
            int j = jj + q4;
            int ss = __shfl_sync(0xffffffffu, s, j < cnt ? j : 0);
            if (j < cnt) acc8_add(acc, H[(size_t)ss * 8 + fl]);
        }
    }
    #pragma unroll
    for (int i = 0; i < 8; i++) {
        acc[i] += __shfl_xor_sync(0xffffffffu, acc[i], 8);
        acc[i] += __shfl_xor_sync(0xffffffffu, acc[i], 16);
    }
    if (lane < 8) {
        float dd = g_dinv[gw];
        float4 b0 = *(const float4*)&bias[fl * 8];
        float4 b1 = *(const float4*)&bias[fl * 8 + 4];
        __half2 o[4];
        o[0] = __floats2half2_rn(fmaxf(acc[0] * dd + b0.x, 0.f), fmaxf(acc[1] * dd + b0.y, 0.f));
        o[1] = __floats2half2_rn(fmaxf(acc[2] * dd + b0.z, 0.f), fmaxf(acc[3] * dd + b0.w, 0.f));
        o[2] = __floats2half2_rn(fmaxf(acc[4] * dd + b1.x, 0.f), fmaxf(acc[5] * dd + b1.y, 0.f));
        o[3] = __floats2half2_rn(fmaxf(acc[6] * dd + b1.z, 0.f), fmaxf(acc[7] * dd + b1.w, 0.f));
        ((uint4*)g_h2_h)[(size_t)gw * 8 + fl] =
            make_uint4(*(uint32_t*)&o[0], *(uint32_t*)&o[1], *(uint32_t*)&o[2], *(uint32_t*)&o[3]);
    }
}

// ---------------- edge scorer fp16x2 HMMA ----------------
// halves: Th@0(9216) Tl@9216 Wh@18432(4608) -> 23040 halves = 46080 B
// floats after: w2s@46080 (128), b1s@46592 (64) -> total 46848 B
#define SC_SMEM 46848

__global__ void __launch_bounds__(256, 1)
k_score_mma(const int* __restrict__ la, const int* __restrict__ lb,
            const float* __restrict__ fcb1,
            const float* __restrict__ fcW2, const float* __restrict__ fcb2,
            float* __restrict__ out) {
    extern __shared__ __half smh[];
    __half* Th = smh;
    __half* Tl = smh + 9216;
    __half* Wh = smh + 18432;
    float* w2s = (float*)((char*)smh + 46080);
    float* b1s = (float*)((char*)smh + 46592);
    const int tid = threadIdx.x, lane = tid & 31, wid = tid >> 5;
    const int gid = lane >> 2, tq = lane & 3;
    const int e0 = blockIdx.x * 128;
    const int lt = lane >> 3, lr = lane & 7;
    const int arow = (lt & 1) * 8 + lr, acol = (lt >> 1) * 8;
    const int bn = (lt >> 1) * 8 + lr, bk = (lt & 1) * 8;

    #pragma unroll
    for (int l = 0; l < 2; l++) {
        int j = tid + l * 256;               // 512 chunks: 64 rows x 8
        int n = j >> 3, c8 = j & 7;
        const __half* g = g_fw1h + (size_t)n * 64 + c8 * 8;
        uint32_t sa = smem_u32(Wh + n * 72 + c8 * 8);
        asm volatile("cp.async.cg.shared.global [%0], [%1], 16;\n" :: "r"(sa), "l"(g));
    }
    asm volatile("cp.async.commit_group;\n");
    if (tid < 128) w2s[tid] = fcW2[tid];
    if (tid < 64)  b1s[tid] = fcb1[tid];

    #pragma unroll
    for (int l = 0; l < 4; l++) {
        int idx = tid + l * 256;             // 1024 = 128 edges x 8 chunks
        int e = idx >> 3, c8 = idx & 7;
        int eg = e0 + e;
        if (eg >= NL) eg = NL - 1;
        int a = la[eg], b = lb[eg];
        uint4 va = *(const uint4*)&g_h2_h[(size_t)a * H2 + c8 * 8];
        uint4 vb = *(const uint4*)&g_h2_h[(size_t)b * H2 + c8 * 8];
        uint32_t th[4], tl[4];
        const uint32_t* pa = (const uint32_t*)&va;
        const uint32_t* pb = (const uint32_t*)&vb;
        #pragma unroll
        for (int q = 0; q < 4; q++) {
            float2 fa = __half22float2(*(__half2*)&pa[q]);
            float2 fb = __half22float2(*(__half2*)&pb[q]);
            float px = fa.x * fb.x, py = fa.y * fb.y;
            __half hx = __float2half_rn(px), hy = __float2half_rn(py);
            __half lx = __float2half_rn(px - __half2float(hx));
            __half ly = __float2half_rn(py - __half2float(hy));
            __half2 hh = __halves2half2(hx, hy), ll = __halves2half2(lx, ly);
            th[q] = *(uint32_t*)&hh;
            tl[q] = *(uint32_t*)&ll;
        }
        *(uint4*)&Th[e * 72 + c8 * 8] = make_uint4(th[0], th[1], th[2], th[3]);
        *(uint4*)&Tl[e * 72 + c8 * 8] = make_uint4(tl[0], tl[1], tl[2], tl[3]);
    }
    asm volatile("cp.async.wait_group 0;\n");
    __syncthreads();

    float acc[8][4];
    #pragma unroll
    for (int nt = 0; nt < 8; nt++)
        #pragma unroll
        for (int i = 0; i < 4; i++) acc[nt][i] = 0.f;

    const int rowT = wid * 16;
    #pragma unroll
    for (int ks = 0; ks < 4; ks++) {
        int kb = ks * 16;
        uint32_t ah[4], al[4];
        ldsm_x4(ah, smem_u32(&Th[(rowT + arow) * 72 + kb + acol]));
        ldsm_x4(al, smem_u32(&Tl[(rowT + arow) * 72 + kb + acol]));
        uint32_t bh[8][2];
        #pragma unroll
        for (int g2 = 0; g2 < 4; g2++) {
            uint32_t tb[4];
            ldsm_x4(tb, smem_u32(&Wh[(g2 * 16 + bn) * 72 + kb + bk]));
            bh[g2 * 2][0] = tb[0]; bh[g2 * 2][1] = tb[1];
            bh[g2 * 2 + 1][0] = tb[2]; bh[g2 * 2 + 1][1] = tb[3];
        }
        #pragma unroll
        for (int nt = 0; nt < 8; nt++) {
            HMMA(acc[nt], ah, bh[nt]);
            HMMA(acc[nt], al, bh[nt]);
        }
    }

    // second tiny layer in registers
    float p00 = 0.f, p01 = 0.f, p10 = 0.f, p11 = 0.f;
    #pragma unroll
    for (int nt = 0; nt < 8; nt++) {
        int col = nt * 8 + tq * 2;
        float4 w2a = *(float4*)&w2s[col * 2];
        float b0v = b1s[col], b1v = b1s[col + 1];
        float u0 = fmaxf(acc[nt][0] + b0v, 0.f);
        float u1 = fmaxf(acc[nt][1] + b1v, 0.f);
        float u2 = fmaxf(acc[nt][2] + b0v, 0.f);
        float u3 = fmaxf(acc[nt][3] + b1v, 0.f);
        p00 += u0 * w2a.x + u1 * w2a.z;
        p01 += u0 * w2a.y + u1 * w2a.w;
        p10 += u2 * w2a.x + u3 * w2a.z;
        p11 += u2 * w2a.y + u3 * w2a.w;
    }
    #pragma unroll
    for (int off = 1; off <= 2; off <<= 1) {
        p00 += __shfl_xor_sync(0xffffffffu, p00, off);
        p01 += __shfl_xor_sync(0xffffffffu, p01, off);
        p10 += __shfl_xor_sync(0xffffffffu, p10, off);
        p11 += __shfl_xor_sync(0xffffffffu, p11, off);
    }
    if (tq == 0) {
        float c0 = fcb2[0], c1 = fcb2[1];
        int e = e0 + wid * 16 + gid;
        if (e < NL)     *(float2*)&out[(size_t)e * 2]       = make_float2(p00 + c0, p01 + c1);
        if (e + 8 < NL) *(float2*)&out[(size_t)(e + 8) * 2] = make_float2(p10 + c0, p11 + c1);
    }
}

// ---------------- launch ----------------
extern "C" void kernel_launch(void* const* d_in, const int* in_sizes, int n_in,
                              void* d_out, int out_size) {
    const float* x    = (const float*)d_in[0];
    const float* W1   = (const float*)d_in[1];
    const float* b1   = (const float*)d_in[2];
    const float* W2   = (const float*)d_in[3];
    const float* b2   = (const float*)d_in[4];
    const float* fcW1 = (const float*)d_in[5];
    const float* fcb1 = (const float*)d_in[6];
    const float* fcW2 = (const float*)d_in[7];
    const float* fcb2 = (const float*)d_in[8];
    const int* eidx = (const int*)d_in[9];
    const int* elab = (const int*)d_in[10];
    const int* src = eidx;
    const int* dst = eidx + NE;
    const int* la = elab;
    const int* lb = elab + NL;
    float* out = (float*)d_out;

    static int attr_done = 0;
    static cudaStream_t s2;
    static cudaEvent_t evA, evB;
    if (!attr_done) {
        cudaFuncSetAttribute(k_gemm1_mma, cudaFuncAttributeMaxDynamicSharedMemorySize, G1_SMEM);
        cudaFuncSetAttribute(k_gemm2_mma, cudaFuncAttributeMaxDynamicSharedMemorySize, G2_SMEM);
        cudaFuncSetAttribute(k_score_mma, cudaFuncAttributeMaxDynamicSharedMemorySize, SC_SMEM);
        cudaStreamCreateWithFlags(&s2, cudaStreamNonBlocking);
        cudaEventCreateWithFlags(&evA, cudaEventDisableTiming);
        cudaEventCreateWithFlags(&evB, cudaEventDisableTiming);
        attr_done = 1;
    }

    // full fork: entire CSR chain on s2, weight prep + gemm1 on default
    cudaEventRecord(evA, 0);
    cudaStreamWaitEvent(s2, evA, 0);

    k_zero_count<<<(NN + 255) / 256, 256, 0, s2>>>();
    k_hist<<<(NE + 255) / 256, 256, 0, s2>>>(dst);
    k_dinv<<<(NN + 255) / 256, 256, 0, s2>>>();
    k_bsum<<<NBLK, 1024, 0, s2>>>();
    k_bscan<<<1, 128, 0, s2>>>();
    k_scat<<<NBLK, 1024, 0, s2>>>();
    k_fill<<<(NE + 255) / 256, 256, 0, s2>>>(src, dst);
    cudaEventRecord(evB, s2);

    k_wsplit<<<(H1 * F_IN + 255) / 256, 256>>>(W1);
    k_wsplit2<<<(H2 * H1 + 255) / 256, 256>>>(W2);
    k_wsplitFC<<<(64 * 64 + 255) / 256, 256>>>(fcW1);
    k_gemm1_mma<<<(NN + 127) / 128, 256, G1_SMEM>>>(x);

    // join
    cudaStreamWaitEvent(0, evB, 0);

    k_scale1<<<(NN * 16 + 255) / 256, 256>>>();
    k_agg128<<<(NN * 32 + 255) / 256, 256>>>(b1);
    k_gemm2_mma<<<(NN + 127) / 128, 256, G2_SMEM>>>();
    k_agg64<<<(NN * 32 + 255) / 256, 256>>>(b2);
    k_score_mma<<<(NL + 127) / 128, 256, SC_SMEM>>>(la, lb, fcb1, fcW2, fcb2, out);
}

// round 10
// speedup vs baseline: 1.2792x; 1.1048x over previous
#include <cuda_runtime.h>
#include <cuda_fp16.h>
#include <math.h>
#include <stdint.h>

#define NN 100000
#define NE 3200000
#define NL 1000000
#define F_IN 512
#define H1 128
#define H2 64
#define NBLK ((NN + 1023) / 1024)

// ---------------- scratch (static device globals; no allocs) ----------------
__device__ __half g_h1lin_s[(size_t)NN * H1];   // pre-agg layer1 (unscaled, then scaled in place)
__device__ __half g_h1_h  [(size_t)NN * H1];    // fp16 post-relu layer1
__device__ __half g_h2lin_s[(size_t)NN * H2];   // fp16 dinv-scaled pre-agg layer2
__device__ __half g_h2_h  [(size_t)NN * H2];    // fp16 post-relu layer2
__device__ float  g_dinv [NN];
__device__ int    g_count[NN];
__device__ int    g_rowptr[NN + 1];
__device__ int    g_cursor[NN];
__device__ int    g_csr  [NE];
__device__ int    g_bsum [NBLK];
__device__ int    g_bpre [NBLK];
__device__ __half g_w1h[(size_t)H1 * F_IN];     // W1^T fp16 [128][512]
__device__ __half g_w2h[(size_t)H2 * H1];       // W2^T fp16 [64][128]
__device__ __half g_fw1h[(size_t)64 * 64];      // fcW1^T fp16 [64n][64k]

// ---------------- helpers ----------------
__device__ __forceinline__ uint32_t smem_u32(const void* p) {
    uint32_t a;
    asm("{ .reg .u64 t; cvta.to.shared.u64 t, %1; cvt.u32.u64 %0, t; }" : "=r"(a) : "l"(p));
    return a;
}
#define HMMA(c, a, b) \
    asm volatile("mma.sync.aligned.m16n8k16.row.col.f32.f16.f16.f32 " \
                 "{%0,%1,%2,%3}, {%4,%5,%6,%7}, {%8,%9}, {%0,%1,%2,%3};" \
                 : "+f"((c)[0]), "+f"((c)[1]), "+f"((c)[2]), "+f"((c)[3]) \
                 : "r"((a)[0]), "r"((a)[1]), "r"((a)[2]), "r"((a)[3]), \
                   "r"((b)[0]), "r"((b)[1]))

__device__ __forceinline__ void ldsm_x4(uint32_t* r, uint32_t addr) {
    asm volatile("ldmatrix.sync.aligned.m8n8.x4.shared.b16 {%0,%1,%2,%3}, [%4];"
                 : "=r"(r[0]), "=r"(r[1]), "=r"(r[2]), "=r"(r[3]) : "r"(addr));
}

__device__ __forceinline__ void acc8_add(float* acc, uint4 v) {
    const uint32_t* p = (const uint32_t*)&v;
    #pragma unroll
    for (int q = 0; q < 4; q++) {
        float2 f = __half22float2(*(__half2*)&p[q]);
        acc[q * 2] += f.x;
        acc[q * 2 + 1] += f.y;
    }
}

// ---------------- CSR build ----------------
__global__ void k_hist(const int* __restrict__ dst) {
    int i = blockIdx.x * blockDim.x + threadIdx.x;
    if (i < NE) atomicAdd(&g_count[dst[i]], 1);
}
__global__ void k_dinv() {
    int i = blockIdx.x * blockDim.x + threadIdx.x;
    if (i < NN) g_dinv[i] = rsqrtf((float)(g_count[i] + 1));
}
__global__ void k_bsum() {
    __shared__ int ws[32];
    int t = threadIdx.x, lane = t & 31, wid = t >> 5;
    int i = blockIdx.x * 1024 + t;
    int v = (i < NN) ? g_count[i] : 0;
    #pragma unroll
    for (int o = 16; o; o >>= 1) v += __shfl_down_sync(0xffffffffu, v, o);
    if (lane == 0) ws[wid] = v;
    __syncthreads();
    if (wid == 0) {
        int x = ws[lane];
        #pragma unroll
        for (int o = 16; o; o >>= 1) x += __shfl_down_sync(0xffffffffu, x, o);
        if (lane == 0) g_bsum[blockIdx.x] = x;
    }
}
__global__ void k_bscan() {
    __shared__ int ws[4];
    int t = threadIdx.x, lane = t & 31, wid = t >> 5;
    int v = (t < NBLK) ? g_bsum[t] : 0;
    int x = v;
    #pragma unroll
    for (int o = 1; o < 32; o <<= 1) {
        int y = __shfl_up_sync(0xffffffffu, x, o);
        if (lane >= o) x += y;
    }
    if (lane == 31) ws[wid] = x;
    __syncthreads();
    int add = 0;
    for (int w = 0; w < wid; w++) add += ws[w];
    int incl = x + add;
    if (t < NBLK) g_bpre[t] = incl - v;
    if (t == 127) g_rowptr[NN] = incl;
}
__global__ void k_scat() {
    __shared__ int ws[32];
    int t = threadIdx.x, lane = t & 31, wid = t >> 5;
    int i = blockIdx.x * 1024 + t;
    int v = (i < NN) ? g_count[i] : 0;
    int x = v;
    #pragma unroll
    for (int o = 1; o < 32; o <<= 1) {
        int y = __shfl_up_sync(0xffffffffu, x, o);
        if (lane >= o) x += y;
    }
    if (lane == 31) ws[wid] = x;
    __syncthreads();
    if (wid == 0) {
        int w = ws[lane];
        #pragma unroll
        for (int o = 1; o < 32; o <<= 1) {
            int y = __shfl_up_sync(0xffffffffu, w, o);
            if (lane >= o) w += y;
        }
        ws[lane] = w;
    }
    __syncthreads();
    int excl = g_bpre[blockIdx.x] + (wid ? ws[wid - 1] : 0) + x - v;
    if (i < NN) { g_rowptr[i] = excl; g_cursor[i] = excl; }
}
__global__ void k_fill(const int* __restrict__ src, const int* __restrict__ dst) {
    int i = blockIdx.x * blockDim.x + threadIdx.x;
    if (i < NE) {
        int p = atomicAdd(&g_cursor[dst[i]], 1);
        g_csr[p] = src[i];
    }
}

// ---------------- combined weight transpose (fp16) ----------------
#define WP_N (H1 * F_IN + H2 * H1 + 64 * 64)
__global__ void k_wprep(const float* __restrict__ W1, const float* __restrict__ W2,
                        const float* __restrict__ fcW1) {
    int i = blockIdx.x * blockDim.x + threadIdx.x;
    if (i < H1 * F_IN) {
        int n = i & (H1 - 1), k = i >> 7;
        g_w1h[(size_t)n * F_IN + k] = __float2half_rn(W1[(size_t)k * H1 + n]);
    } else if (i < H1 * F_IN + H2 * H1) {
        int j = i - H1 * F_IN;
        int n = j & (H2 - 1), k = j >> 6;
        g_w2h[(size_t)n * H1 + k] = __float2half_rn(W2[(size_t)k * H2 + n]);
    } else if (i < WP_N) {
        int j = i - H1 * F_IN - H2 * H1;
        int n = j & 63, k = j >> 6;
        g_fw1h[(size_t)n * 64 + k] = __float2half_rn(fcW1[(size_t)k * 64 + n]);
    }
}

// ---------------- GEMM1 fp16x2 HMMA: h1lin = x @ W1 (unscaled) ----------------
// stage (halves, stride 40/row): Ah@0(5120) Al@5120 Bh@10240(5120) -> 15360
#define G1_STAGE_H 15360
#define G1_SMEM (2 * G1_STAGE_H * 2)

__global__ void __launch_bounds__(256, 1)
k_gemm1_mma(const float* __restrict__ A) {
    extern __shared__ __half smh[];
    const int tid = threadIdx.x, lane = tid & 31, wid = tid >> 5;
    const int gid = lane >> 2, tq = lane & 3;
    const int rowBase = blockIdx.x * 128;
    const int wm = (wid >> 1) * 32, wn = (wid & 1) * 64;
    const int lt = lane >> 3, lr = lane & 7;
    const int arow = (lt & 1) * 8 + lr, acol = (lt >> 1) * 8;
    const int bn = (lt >> 1) * 8 + lr, bk = (lt & 1) * 8;

    float acc[2][8][4];
    #pragma unroll
    for (int mt = 0; mt < 2; mt++)
        #pragma unroll
        for (int nt = 0; nt < 8; nt++)
            #pragma unroll
            for (int i = 0; i < 4; i++) acc[mt][nt][i] = 0.f;

    float4 pa[4];
    auto ldgA = [&](int kt) {
        #pragma unroll
        for (int l = 0; l < 4; l++) {
            int f = tid + l * 256;
            int row = f >> 3, c4 = f & 7;
            int gr = rowBase + row;
            pa[l] = (gr < NN) ? *(const float4*)&A[(size_t)gr * F_IN + kt + c4 * 4]
                              : make_float4(0.f, 0.f, 0.f, 0.f);
        }
    };
    auto stsA = [&](__half* buf) {
        #pragma unroll
        for (int l = 0; l < 4; l++) {
            int f = tid + l * 256;
            int row = f >> 3, c4 = f & 7;
            float4 v = pa[l];
            __half hx = __float2half_rn(v.x), hy = __float2half_rn(v.y);
            __half hz = __float2half_rn(v.z), hw = __float2half_rn(v.w);
            __half lx = __float2half_rn(v.x - __half2float(hx));
            __half ly = __float2half_rn(v.y - __half2float(hy));
            __half lz = __float2half_rn(v.z - __half2float(hz));
            __half lw = __float2half_rn(v.w - __half2float(hw));
            __half2 h0 = __halves2half2(hx, hy), h1v = __halves2half2(hz, hw);
            __half2 l0 = __halves2half2(lx, ly), l1v = __halves2half2(lz, lw);
            *(uint2*)&buf[row * 40 + c4 * 4] =
                make_uint2(*(uint32_t*)&h0, *(uint32_t*)&h1v);
            *(uint2*)&buf[5120 + row * 40 + c4 * 4] =
                make_uint2(*(uint32_t*)&l0, *(uint32_t*)&l1v);
        }
    };
    auto cpB = [&](int kt, __half* buf) {
        #pragma unroll
        for (int l = 0; l < 2; l++) {
            int j = tid + l * 256;          // 512 chunks: 128 rows x 4
            int r = j >> 2, c8 = j & 3;
            const __half* g = g_w1h + (size_t)r * F_IN + kt + c8 * 8;
            uint32_t sa = smem_u32(buf + 10240 + r * 40 + c8 * 8);
            asm volatile("cp.async.cg.shared.global [%0], [%1], 16;\n" :: "r"(sa), "l"(g));
        }
        asm volatile("cp.async.commit_group;\n");
    };

    ldgA(0);
    cpB(0, smh);
    stsA(smh);
    asm volatile("cp.async.wait_group 0;\n");
    __syncthreads();

    for (int s = 0; s < 16; s++) {
        __half* cur = smh + (s & 1) * G1_STAGE_H;
        __half* nxt = smh + ((s + 1) & 1) * G1_STAGE_H;
        if (s + 1 < 16) { cpB((s + 1) * 32, nxt); ldgA((s + 1) * 32); }

        const __half* Ah = cur;
        const __half* Al = cur + 5120;
        const __half* Bh = cur + 10240;

        #pragma unroll
        for (int ks = 0; ks < 2; ks++) {
            int kb = ks * 16;
            uint32_t ah[2][4], al[2][4];
            #pragma unroll
            for (int mt = 0; mt < 2; mt++) {
                ldsm_x4(ah[mt], smem_u32(&Ah[(wm + mt * 16 + arow) * 40 + kb + acol]));
                ldsm_x4(al[mt], smem_u32(&Al[(wm + mt * 16 + arow) * 40 + kb + acol]));
            }
            uint32_t bh[8][2];
            #pragma unroll
            for (int g2 = 0; g2 < 4; g2++) {
                uint32_t tb[4];
                ldsm_x4(tb, smem_u32(&Bh[(wn + g2 * 16 + bn) * 40 + kb + bk]));
                bh[g2 * 2][0] = tb[0]; bh[g2 * 2][1] = tb[1];
                bh[g2 * 2 + 1][0] = tb[2]; bh[g2 * 2 + 1][1] = tb[3];
            }
            #pragma unroll
            for (int mt = 0; mt < 2; mt++)
                #pragma unroll
                for (int nt = 0; nt < 8; nt++) {
                    HMMA(acc[mt][nt], ah[mt], bh[nt]);
                    HMMA(acc[mt][nt], al[mt], bh[nt]);
                }
        }
        if (s + 1 < 16) { stsA(nxt); asm volatile("cp.async.wait_group 0;\n"); }
        __syncthreads();
    }

    #pragma unroll
    for (int mt = 0; mt < 2; mt++) {
        int row = rowBase + wm + mt * 16 + gid;
        #pragma unroll
        for (int nt = 0; nt < 8; nt++) {
            int col = wn + nt * 8 + tq * 2;
            if (row < NN)
                *(__half2*)&g_h1lin_s[(size_t)row * H1 + col] =
                    __floats2half2_rn(acc[mt][nt][0], acc[mt][nt][1]);
            if (row + 8 < NN)
                *(__half2*)&g_h1lin_s[(size_t)(row + 8) * H1 + col] =
                    __floats2half2_rn(acc[mt][nt][2], acc[mt][nt][3]);
        }
    }
}

// ---------------- scale h1lin in place by dinv[row] ----------------
__global__ void k_scale1() {
    int i = blockIdx.x * blockDim.x + threadIdx.x;   // uint4 id, NN*16 total
    if (i < NN * 16) {
        int row = i >> 4;
        float dd = g_dinv[row];
        uint4 v = ((uint4*)g_h1lin_s)[i];
        uint32_t* p = (uint32_t*)&v;
        #pragma unroll
        for (int q = 0; q < 4; q++) {
            float2 f = __half22float2(*(__half2*)&p[q]);
            __half2 o = __floats2half2_rn(f.x * dd, f.y * dd);
            p[q] = *(uint32_t*)&o;
        }
        ((uint4*)g_h1lin_s)[i] = v;
    }
}

// ---------------- GEMM2 fp16x1 HMMA: h2lin_s = dinv * (h1 @ W2h) ----------------
#define G2_STAGE_H 7680
#define G2_SMEM (2 * G2_STAGE_H * 2)

__global__ void __launch_bounds__(256, 1)
k_gemm2_mma() {
    extern __shared__ __half smh[];
    const int tid = threadIdx.x, lane = tid & 31, wid = tid >> 5;
    const int gid = lane >> 2, tq = lane & 3;
    const int rowBase = blockIdx.x * 128;
    const int wm = wid * 16;
    const int lt = lane >> 3, lr = lane & 7;
    const int arow = (lt & 1) * 8 + lr, acol = (lt >> 1) * 8;
    const int bn = (lt >> 1) * 8 + lr, bk = (lt & 1) * 8;

    float acc[8][4];
    #pragma unroll
    for (int nt = 0; nt < 8; nt++)
        #pragma unroll
        for (int i = 0; i < 4; i++) acc[nt][i] = 0.f;

    auto cpStage = [&](int kt, __half* buf) {
        #pragma unroll
        for (int l = 0; l < 2; l++) {
            int idx = tid + l * 256;
            int r = idx >> 2, c8 = idx & 3;
            int gr = rowBase + r;
            if (gr >= NN) gr = NN - 1;
            const __half* g = g_h1_h + (size_t)gr * H1 + kt + c8 * 8;
            uint32_t sa = smem_u32(buf + r * 40 + c8 * 8);
            asm volatile("cp.async.cg.shared.global [%0], [%1], 16;\n" :: "r"(sa), "l"(g));
        }
        {
            int idx = tid;                  // 256 chunks: 64 rows x 4
            int r = idx >> 2, c8 = idx & 3;
            const __half* g = g_w2h + (size_t)r * H1 + kt + c8 * 8;
            uint32_t sa = smem_u32(buf + 5120 + r * 40 + c8 * 8);
            asm volatile("cp.async.cg.shared.global [%0], [%1], 16;\n" :: "r"(sa), "l"(g));
        }
        asm volatile("cp.async.commit_group;\n");
    };

    cpStage(0, smh);
    asm volatile("cp.async.wait_group 0;\n");
    __syncthreads();

    for (int s = 0; s < 4; s++) {
        __half* cur = smh + (s & 1) * G2_STAGE_H;
        __half* nxt = smh + ((s + 1) & 1) * G2_STAGE_H;
        if (s + 1 < 4) cpStage((s + 1) * 32, nxt);

        const __half* Ah = cur;
        const __half* Bh = cur + 5120;

        #pragma unroll
        for (int ks = 0; ks < 2; ks++) {
            int kb = ks * 16;
            uint32_t a[4];
            ldsm_x4(a, smem_u32(&Ah[(wm + arow) * 40 + kb + acol]));
            uint32_t bh[8][2];
            #pragma unroll
            for (int g2 = 0; g2 < 4; g2++) {
                uint32_t tb[4];
                ldsm_x4(tb, smem_u32(&Bh[(g2 * 16 + bn) * 40 + kb + bk]));
                bh[g2 * 2][0] = tb[0]; bh[g2 * 2][1] = tb[1];
                bh[g2 * 2 + 1][0] = tb[2]; bh[g2 * 2 + 1][1] = tb[3];
            }
            #pragma unroll
            for (int nt = 0; nt < 8; nt++)
                HMMA(acc[nt], a, bh[nt]);
        }
        if (s + 1 < 4) asm volatile("cp.async.wait_group 0;\n");
        __syncthreads();
    }

    int row = rowBase + wm + gid;
    float dv0 = (row < NN) ? g_dinv[row] : 0.f;
    float dv1 = (row + 8 < NN) ? g_dinv[row + 8] : 0.f;
    #pragma unroll
    for (int nt = 0; nt < 8; nt++) {
        int col = nt * 8 + tq * 2;
        if (row < NN)
            *(__half2*)&g_h2lin_s[(size_t)row * H2 + col] =
                __floats2half2_rn(acc[nt][0] * dv0, acc[nt][1] * dv0);
        if (row + 8 < NN)
            *(__half2*)&g_h2lin_s[(size_t)(row + 8) * H2 + col] =
                __floats2half2_rn(acc[nt][2] * dv1, acc[nt][3] * dv1);
    }
}

// ---------------- aggregation: pure row-sum of pre-scaled fp16 rows ----------------
__global__ void k_agg128(const float* __restrict__ bias) {
    int gw = (blockIdx.x * blockDim.x + threadIdx.x) >> 5;
    int lane = threadIdx.x & 31;
    if (gw >= NN) return;
    int half = lane >> 4, fl = lane & 15;
    const uint4* H = (const uint4*)g_h1lin_s;
    float acc[8];
    #pragma unroll
    for (int i = 0; i < 8; i++) acc[i] = 0.f;
    if (half == 0) acc8_add(acc, H[(size_t)gw * 16 + fl]);
    int s0 = g_rowptr[gw], s1 = g_rowptr[gw + 1];
    for (int base = s0; base < s1; base += 32) {
        int rem = s1 - base;
        int cnt = rem < 32 ? rem : 32;
        int s = (lane < rem) ? g_csr[base + lane] : 0;
        int jj = 0;
        for (; jj + 4 <= cnt; jj += 4) {
            int ss0 = __shfl_sync(0xffffffffu, s, jj + half);
            int ss1 = __shfl_sync(0xffffffffu, s, jj + 2 + half);
            uint4 v0 = H[(size_t)ss0 * 16 + fl];
            uint4 v1 = H[(size_t)ss1 * 16 + fl];
            acc8_add(acc, v0);
            acc8_add(acc, v1);
        }
        for (; jj < cnt; jj += 2) {
            int j = jj + half;
            int ss = __shfl_sync(0xffffffffu, s, j < cnt ? j : 0);
            if (j < cnt) acc8_add(acc, H[(size_t)ss * 16 + fl]);
        }
    }
    #pragma unroll
    for (int i = 0; i < 8; i++) acc[i] += __shfl_xor_sync(0xffffffffu, acc[i], 16);
    if (half == 0) {
        float dd = g_dinv[gw];
        float4 b0 = *(const float4*)&bias[fl * 8];
        float4 b1 = *(const float4*)&bias[fl * 8 + 4];
        __half2 o[4];
        o[0] = __floats2half2_rn(fmaxf(acc[0] * dd + b0.x, 0.f), fmaxf(acc[1] * dd + b0.y, 0.f));
        o[1] = __floats2half2_rn(fmaxf(acc[2] * dd + b0.z, 0.f), fmaxf(acc[3] * dd + b0.w, 0.f));
        o[2] = __floats2half2_rn(fmaxf(acc[4] * dd + b1.x, 0.f), fmaxf(acc[5] * dd + b1.y, 0.f));
        o[3] = __floats2half2_rn(fmaxf(acc[6] * dd + b1.z, 0.f), fmaxf(acc[7] * dd + b1.w, 0.f));
        ((uint4*)g_h1_h)[(size_t)gw * 16 + fl] =
            make_uint4(*(uint32_t*)&o[0], *(uint32_t*)&o[1], *(uint32_t*)&o[2], *(uint32_t*)&o[3]);
    }
}

__global__ void k_agg64(const float* __restrict__ bias) {
    int gw = (blockIdx.x * blockDim.x + threadIdx.x) >> 5;
    int lane = threadIdx.x & 31;
    if (gw >= NN) return;
    int q4 = lane >> 3, fl = lane & 7;
    const uint4* H = (const uint4*)g_h2lin_s;
    float acc[8];
    #pragma unroll
    for (int i = 0; i < 8; i++) acc[i] = 0.f;
    if (q4 == 0) acc8_add(acc, H[(size_t)gw * 8 + fl]);
    int s0 = g_rowptr[gw], s1 = g_rowptr[gw + 1];
    for (int base = s0; base < s1; base += 32) {
        int rem = s1 - base;
        int cnt = rem < 32 ? rem : 32;
        int s = (lane < rem) ? g_csr[base + lane] : 0;
        int jj = 0;
        for (; jj + 8 <= cnt; jj += 8) {
            int ss0 = __shfl_sync(0xffffffffu, s, jj + q4);
            int ss1 = __shfl_sync(0xffffffffu, s, jj + 4 + q4);
            uint4 v0 = H[(size_t)ss0 * 8 + fl];
            uint4 v1 = H[(size_t)ss1 * 8 + fl];
            acc8_add(acc, v0);
            acc8_add(acc, v1);
        }
        for (; jj < cnt; jj += 4) {
            int j = jj + q4;
            int ss = __shfl_sync(0xffffffffu, s, j < cnt ? j : 0);
            if (j < cnt) acc8_add(acc, H[(size_t)ss * 8 + fl]);
        }
    }
    #pragma unroll
    for (int i = 0; i < 8; i++) {
        acc[i] += __shfl_xor_sync(0xffffffffu, acc[i], 8);
        acc[i] += __shfl_xor_sync(0xffffffffu, acc[i], 16);
    }
    if (lane < 8) {
        float dd = g_dinv[gw];
        float4 b0 = *(const float4*)&bias[fl * 8];
        float4 b1 = *(const float4*)&bias[fl * 8 + 4];
        __half2 o[4];
        o[0] = __floats2half2_rn(fmaxf(acc[0] * dd + b0.x, 0.f), fmaxf(acc[1] * dd + b0.y, 0.f));
        o[1] = __floats2half2_rn(fmaxf(acc[2] * dd + b0.z, 0.f), fmaxf(acc[3] * dd + b0.w, 0.f));
        o[2] = __floats2half2_rn(fmaxf(acc[4] * dd + b1.x, 0.f), fmaxf(acc[5] * dd + b1.y, 0.f));
        o[3] = __floats2half2_rn(fmaxf(acc[6] * dd + b1.z, 0.f), fmaxf(acc[7] * dd + b1.w, 0.f));
        ((uint4*)g_h2_h)[(size_t)gw * 8 + fl] =
            make_uint4(*(uint32_t*)&o[0], *(uint32_t*)&o[1], *(uint32_t*)&o[2], *(uint32_t*)&o[3]);
    }
}

// ---------------- edge scorer fp16x1 HMMA ----------------
// halves: Th@0(9216) Wh@9216(4608) -> 13824 halves = 27648 B
// floats after: w2s@27648 (128 f), b1s@28160 (64 f) -> total 28416 B
#define SC_SMEM 28416

__global__ void __launch_bounds__(256)
k_score_mma(const int* __restrict__ la, const int* __restrict__ lb,
            const float* __restrict__ fcb1,
            const float* __restrict__ fcW2, const float* __restrict__ fcb2,
            float* __restrict__ out) {
    extern __shared__ __half smh[];
    __half* Th = smh;
    __half* Wh = smh + 9216;
    float* w2s = (float*)((char*)smh + 27648);
    float* b1s = (float*)((char*)smh + 28160);
    const int tid = threadIdx.x, lane = tid & 31, wid = tid >> 5;
    const int gid = lane >> 2, tq = lane & 3;
    const int e0 = blockIdx.x * 128;
    const int lt = lane >> 3, lr = lane & 7;
    const int arow = (lt & 1) * 8 + lr, acol = (lt >> 1) * 8;
    const int bn = (lt >> 1) * 8 + lr, bk = (lt & 1) * 8;

    #pragma unroll
    for (int l = 0; l < 2; l++) {
        int j = tid + l * 256;               // 512 chunks: 64 rows x 8
        int n = j >> 3, c8 = j & 7;
        const __half* g = g_fw1h + (size_t)n * 64 + c8 * 8;
        uint32_t sa = smem_u32(Wh + n * 72 + c8 * 8);
        asm volatile("cp.async.cg.shared.global [%0], [%1], 16;\n" :: "r"(sa), "l"(g));
    }
    asm volatile("cp.async.commit_group;\n");
    if (tid < 128) w2s[tid] = fcW2[tid];
    if (tid < 64)  b1s[tid] = fcb1[tid];

    #pragma unroll
    for (int l = 0; l < 4; l++) {
        int idx = tid + l * 256;             // 1024 = 128 edges x 8 chunks
        int e = idx >> 3, c8 = idx & 7;
        int eg = e0 + e;
        if (eg >= NL) eg = NL - 1;
        int a = la[eg], b = lb[eg];
        uint4 va = *(const uint4*)&g_h2_h[(size_t)a * H2 + c8 * 8];
        uint4 vb = *(const uint4*)&g_h2_h[(size_t)b * H2 + c8 * 8];
        uint32_t th[4];
        const uint32_t* pa = (const uint32_t*)&va;
        const uint32_t* pb = (const uint32_t*)&vb;
        #pragma unroll
        for (int q = 0; q < 4; q++) {
            float2 fa = __half22float2(*(__half2*)&pa[q]);
            float2 fb = __half22float2(*(__half2*)&pb[q]);
            __half2 hh = __floats2half2_rn(fa.x * fb.x, fa.y * fb.y);
            th[q] = *(uint32_t*)&hh;
        }
        *(uint4*)&Th[e * 72 + c8 * 8] = make_uint4(th[0], th[1], th[2], th[3]);
    }
    asm volatile("cp.async.wait_group 0;\n");
    __syncthreads();

    float acc[8][4];
    #pragma unroll
    for (int nt = 0; nt < 8; nt++)
        #pragma unroll
        for (int i = 0; i < 4; i++) acc[nt][i] = 0.f;

    const int rowT = wid * 16;
    #pragma unroll
    for (int ks = 0; ks < 4; ks++) {
        int kb = ks * 16;
        uint32_t ah[4];
        ldsm_x4(ah, smem_u32(&Th[(rowT + arow) * 72 + kb + acol]));
        uint32_t bh[8][2];
        #pragma unroll
        for (int g2 = 0; g2 < 4; g2++) {
            uint32_t tb[4];
            ldsm_x4(tb, smem_u32(&Wh[(g2 * 16 + bn) * 72 + kb + bk]));
            bh[g2 * 2][0] = tb[0]; bh[g2 * 2][1] = tb[1];
            bh[g2 * 2 + 1][0] = tb[2]; bh[g2 * 2 + 1][1] = tb[3];
        }
        #pragma unroll
        for (int nt = 0; nt < 8; nt++)
            HMMA(acc[nt], ah, bh[nt]);
    }

    // second tiny layer in registers
    float p00 = 0.f, p01 = 0.f, p10 = 0.f, p11 = 0.f;
    #pragma unroll
    for (int nt = 0; nt < 8; nt++) {
        int col = nt * 8 + tq * 2;
        float4 w2a = *(float4*)&w2s[col * 2];
        float b0v = b1s[col], b1v = b1s[col + 1];
        float u0 = fmaxf(acc[nt][0] + b0v, 0.f);
        float u1 = fmaxf(acc[nt][1] + b1v, 0.f);
        float u2 = fmaxf(acc[nt][2] + b0v, 0.f);
        float u3 = fmaxf(acc[nt][3] + b1v, 0.f);
        p00 += u0 * w2a.x + u1 * w2a.z;
        p01 += u0 * w2a.y + u1 * w2a.w;
        p10 += u2 * w2a.x + u3 * w2a.z;
        p11 += u2 * w2a.y + u3 * w2a.w;
    }
    #pragma unroll
    for (int off = 1; off <= 2; off <<= 1) {
        p00 += __shfl_xor_sync(0xffffffffu, p00, off);
        p01 += __shfl_xor_sync(0xffffffffu, p01, off);
        p10 += __shfl_xor_sync(0xffffffffu, p10, off);
        p11 += __shfl_xor_sync(0xffffffffu, p11, off);
    }
    if (tq == 0) {
        float c0 = fcb2[0], c1 = fcb2[1];
        int e = e0 + wid * 16 + gid;
        if (e < NL)     *(float2*)&out[(size_t)e * 2]       = make_float2(p00 + c0, p01 + c1);
        if (e + 8 < NL) *(float2*)&out[(size_t)(e + 8) * 2] = make_float2(p10 + c0, p11 + c1);
    }
}

// ---------------- launch ----------------
extern "C" void kernel_launch(void* const* d_in, const int* in_sizes, int n_in,
                              void* d_out, int out_size) {
    const float* x    = (const float*)d_in[0];
    const float* W1   = (const float*)d_in[1];
    const float* b1   = (const float*)d_in[2];
    const float* W2   = (const float*)d_in[3];
    const float* b2   = (const float*)d_in[4];
    const float* fcW1 = (const float*)d_in[5];
    const float* fcb1 = (const float*)d_in[6];
    const float* fcW2 = (const float*)d_in[7];
    const float* fcb2 = (const float*)d_in[8];
    const int* eidx = (const int*)d_in[9];
    const int* elab = (const int*)d_in[10];
    const int* src = eidx;
    const int* dst = eidx + NE;
    const int* la = elab;
    const int* lb = elab + NL;
    float* out = (float*)d_out;

    static int attr_done = 0;
    static cudaStream_t s2;
    static cudaEvent_t evA, evB;
    static void* p_count = nullptr;
    if (!attr_done) {
        cudaFuncSetAttribute(k_gemm1_mma, cudaFuncAttributeMaxDynamicSharedMemorySize, G1_SMEM);
        cudaFuncSetAttribute(k_gemm2_mma, cudaFuncAttributeMaxDynamicSharedMemorySize, G2_SMEM);
        cudaFuncSetAttribute(k_score_mma, cudaFuncAttributeMaxDynamicSharedMemorySize, SC_SMEM);
        cudaStreamCreateWithFlags(&s2, cudaStreamNonBlocking);
        cudaEventCreateWithFlags(&evA, cudaEventDisableTiming);
        cudaEventCreateWithFlags(&evB, cudaEventDisableTiming);
        cudaGetSymbolAddress(&p_count, g_count);
        attr_done = 1;
    }

    // full fork: entire CSR chain on s2, weight prep + gemm1 on default
    cudaEventRecord(evA, 0);
    cudaStreamWaitEvent(s2, evA, 0);

    cudaMemsetAsync(p_count, 0, NN * sizeof(int), s2);
    k_hist<<<(NE + 255) / 256, 256, 0, s2>>>(dst);
    k_dinv<<<(NN + 255) / 256, 256, 0, s2>>>();
    k_bsum<<<NBLK, 1024, 0, s2>>>();
    k_bscan<<<1, 128, 0, s2>>>();
    k_scat<<<NBLK, 1024, 0, s2>>>();
    k_fill<<<(NE + 255) / 256, 256, 0, s2>>>(src, dst);
    cudaEventRecord(evB, s2);

    k_wprep<<<(WP_N + 255) / 256, 256>>>(W1, W2, fcW1);
    k_gemm1_mma<<<(NN + 127) / 128, 256, G1_SMEM>>>(x);

    // join
    cudaStreamWaitEvent(0, evB, 0);

    k_scale1<<<(NN * 16 + 255) / 256, 256>>>();
    k_agg128<<<(NN * 32 + 255) / 256, 256>>>(b1);
    k_gemm2_mma<<<(NN + 127) / 128, 256, G2_SMEM>>>();
    k_agg64<<<(NN * 32 + 255) / 256, 256>>>(b2);
    k_score_mma<<<(NL + 127) / 128, 256, SC_SMEM>>>(la, lb, fcb1, fcW2, fcb2, out);
}

// round 12
// speedup vs baseline: 1.2959x; 1.0131x over previous
#include <cuda_runtime.h>
#include <cuda_fp16.h>
#include <math.h>
#include <stdint.h>

#define NN 100000
#define NE 3200000
#define NL 1000000
#define F_IN 512
#define H1 128
#define H2 64
#define NBLK ((NN + 1023) / 1024)

// ---------------- scratch (static device globals; no allocs) ----------------
__device__ __half g_h1lin_s[(size_t)NN * H1];   // pre-agg layer1 (unscaled, then scaled in place)
__device__ __half g_h1_h  [(size_t)NN * H1];    // fp16 post-relu layer1
__device__ __half g_h2lin_s[(size_t)NN * H2];   // fp16 dinv-scaled pre-agg layer2
__device__ __half g_h2_h  [(size_t)NN * H2];    // fp16 post-relu layer2
__device__ float  g_dinv [NN];
__device__ int    g_count[NN];
__device__ int    g_rowptr[NN + 1];
__device__ int    g_cursor[NN];
__device__ int    g_csr  [NE];
__device__ int    g_bsum [NBLK];
__device__ __half g_w1h[(size_t)H1 * F_IN];     // W1^T fp16 [128][512]
__device__ __half g_w2h[(size_t)H2 * H1];       // W2^T fp16 [64][128]
__device__ __half g_fw1h[(size_t)64 * 64];      // fcW1^T fp16 [64n][64k]

// ---------------- helpers ----------------
__device__ __forceinline__ uint32_t smem_u32(const void* p) {
    uint32_t a;
    asm("{ .reg .u64 t; cvta.to.shared.u64 t, %1; cvt.u32.u64 %0, t; }" : "=r"(a) : "l"(p));
    return a;
}
#define HMMA(c, a, b) \
    asm volatile("mma.sync.aligned.m16n8k16.row.col.f32.f16.f16.f32 " \
                 "{%0,%1,%2,%3}, {%4,%5,%6,%7}, {%8,%9}, {%0,%1,%2,%3};" \
                 : "+f"((c)[0]), "+f"((c)[1]), "+f"((c)[2]), "+f"((c)[3]) \
                 : "r"((a)[0]), "r"((a)[1]), "r"((a)[2]), "r"((a)[3]), \
                   "r"((b)[0]), "r"((b)[1]))

__device__ __forceinline__ void ldsm_x4(uint32_t* r, uint32_t addr) {
    asm volatile("ldmatrix.sync.aligned.m8n8.x4.shared.b16 {%0,%1,%2,%3}, [%4];"
                 : "=r"(r[0]), "=r"(r[1]), "=r"(r[2]), "=r"(r[3]) : "r"(addr));
}

__device__ __forceinline__ void acc8_add(float* acc, uint4 v) {
    const uint32_t* p = (const uint32_t*)&v;
    #pragma unroll
    for (int q = 0; q < 4; q++) {
        float2 f = __half22float2(*(__half2*)&p[q]);
        acc[q * 2] += f.x;
        acc[q * 2 + 1] += f.y;
    }
}

// ---------------- CSR build ----------------
__global__ void k_hist(const int* __restrict__ dst) {
    int i = blockIdx.x * blockDim.x + threadIdx.x;
    if (i < NE) atomicAdd(&g_count[dst[i]], 1);
}
// per-block sums + dinv in one pass
__global__ void k_bsum() {
    __shared__ int ws[32];
    int t = threadIdx.x, lane = t & 31, wid = t >> 5;
    int i = blockIdx.x * 1024 + t;
    int v = (i < NN) ? g_count[i] : 0;
    if (i < NN) g_dinv[i] = rsqrtf((float)(v + 1));
    #pragma unroll
    for (int o = 16; o; o >>= 1) v += __shfl_down_sync(0xffffffffu, v, o);
    if (lane == 0) ws[wid] = v;
    __syncthreads();
    if (wid == 0) {
        int x = ws[lane];
        #pragma unroll
        for (int o = 16; o; o >>= 1) x += __shfl_down_sync(0xffffffffu, x, o);
        if (lane == 0) g_bsum[blockIdx.x] = x;
    }
}
// per-block exclusive scan; computes its own global base from g_bsum (no separate scan kernel)
__global__ void k_scat() {
    __shared__ int ws[32];
    __shared__ int base_sh;
    int t = threadIdx.x, lane = t & 31, wid = t >> 5;

    // base = sum of g_bsum[0 .. blockIdx.x)
    if (t < 128) {
        int v2 = (t < blockIdx.x) ? g_bsum[t] : 0;   // NBLK = 98 <= 128
        #pragma unroll
        for (int o = 16; o; o >>= 1) v2 += __shfl_down_sync(0xffffffffu, v2, o);
        if (lane == 0) ws[t >> 5] = v2;
    }
    __syncthreads();
    if (t == 0) base_sh = ws[0] + ws[1] + ws[2] + ws[3];
    __syncthreads();
    int base = base_sh;
    __syncthreads();

    int i = blockIdx.x * 1024 + t;
    int v = (i < NN) ? g_count[i] : 0;
    int x = v;
    #pragma unroll
    for (int o = 1; o < 32; o <<= 1) {
        int y = __shfl_up_sync(0xffffffffu, x, o);
        if (lane >= o) x += y;
    }
    if (lane == 31) ws[wid] = x;
    __syncthreads();
    if (wid == 0) {
        int w = ws[lane];
        #pragma unroll
        for (int o = 1; o < 32; o <<= 1) {
            int y = __shfl_up_sync(0xffffffffu, w, o);
            if (lane >= o) w += y;
        }
        ws[lane] = w;
    }
    __syncthreads();
    int excl = base + (wid ? ws[wid - 1] : 0) + x - v;
    if (i < NN) { g_rowptr[i] = excl; g_cursor[i] = excl; }
    if (blockIdx.x == NBLK - 1 && t == 0) g_rowptr[NN] = base + ws[31];
}
__global__ void k_fill(const int* __restrict__ src, const int* __restrict__ dst) {
    int i = blockIdx.x * blockDim.x + threadIdx.x;
    if (i < NE) {
        int p = atomicAdd(&g_cursor[dst[i]], 1);
        g_csr[p] = src[i];
    }
}

// ---------------- combined weight transpose (fp16) ----------------
#define WP_N (H1 * F_IN + H2 * H1 + 64 * 64)
__global__ void k_wprep(const float* __restrict__ W1, const float* __restrict__ W2,
                        const float* __restrict__ fcW1) {
    int i = blockIdx.x * blockDim.x + threadIdx.x;
    if (i < H1 * F_IN) {
        int n = i & (H1 - 1), k = i >> 7;
        g_w1h[(size_t)n * F_IN + k] = __float2half_rn(W1[(size_t)k * H1 + n]);
    } else if (i < H1 * F_IN + H2 * H1) {
        int j = i - H1 * F_IN;
        int n = j & (H2 - 1), k = j >> 6;
        g_w2h[(size_t)n * H1 + k] = __float2half_rn(W2[(size_t)k * H2 + n]);
    } else if (i < WP_N) {
        int j = i - H1 * F_IN - H2 * H1;
        int n = j & 63, k = j >> 6;
        g_fw1h[(size_t)n * 64 + k] = __float2half_rn(fcW1[(size_t)k * 64 + n]);
    }
}

// ---------------- GEMM1 fp16x2 HMMA: h1lin = x @ W1 (unscaled) ----------------
#define G1_STAGE_H 15360
#define G1_SMEM (2 * G1_STAGE_H * 2)

__global__ void __launch_bounds__(256, 1)
k_gemm1_mma(const float* __restrict__ A) {
    extern __shared__ __half smh[];
    const int tid = threadIdx.x, lane = tid & 31, wid = tid >> 5;
    const int gid = lane >> 2, tq = lane & 3;
    const int rowBase = blockIdx.x * 128;
    const int wm = (wid >> 1) * 32, wn = (wid & 1) * 64;
    const int lt = lane >> 3, lr = lane & 7;
    const int arow = (lt & 1) * 8 + lr, acol = (lt >> 1) * 8;
    const int bn = (lt >> 1) * 8 + lr, bk = (lt & 1) * 8;

    float acc[2][8][4];
    #pragma unroll
    for (int mt = 0; mt < 2; mt++)
        #pragma unroll
        for (int nt = 0; nt < 8; nt++)
            #pragma unroll
            for (int i = 0; i < 4; i++) acc[mt][nt][i] = 0.f;

    float4 pa[4];
    auto ldgA = [&](int kt) {
        #pragma unroll
        for (int l = 0; l < 4; l++) {
            int f = tid + l * 256;
            int row = f >> 3, c4 = f & 7;
            int gr = rowBase + row;
            pa[l] = (gr < NN) ? *(const float4*)&A[(size_t)gr * F_IN + kt + c4 * 4]
                              : make_float4(0.f, 0.f, 0.f, 0.f);
        }
    };
    auto stsA = [&](__half* buf) {
        #pragma unroll
        for (int l = 0; l < 4; l++) {
            int f = tid + l * 256;
            int row = f >> 3, c4 = f & 7;
            float4 v = pa[l];
            __half hx = __float2half_rn(v.x), hy = __float2half_rn(v.y);
            __half hz = __float2half_rn(v.z), hw = __float2half_rn(v.w);
            __half lx = __float2half_rn(v.x - __half2float(hx));
            __half ly = __float2half_rn(v.y - __half2float(hy));
            __half lz = __float2half_rn(v.z - __half2float(hz));
            __half lw = __float2half_rn(v.w - __half2float(hw));
            __half2 h0 = __halves2half2(hx, hy), h1v = __halves2half2(hz, hw);
            __half2 l0 = __halves2half2(lx, ly), l1v = __halves2half2(lz, lw);
            *(uint2*)&buf[row * 40 + c4 * 4] =
                make_uint2(*(uint32_t*)&h0, *(uint32_t*)&h1v);
            *(uint2*)&buf[5120 + row * 40 + c4 * 4] =
                make_uint2(*(uint32_t*)&l0, *(uint32_t*)&l1v);
        }
    };
    auto cpB = [&](int kt, __half* buf) {
        #pragma unroll
        for (int l = 0; l < 2; l++) {
            int j = tid + l * 256;
            int r = j >> 2, c8 = j & 3;
            const __half* g = g_w1h + (size_t)r * F_IN + kt + c8 * 8;
            uint32_t sa = smem_u32(buf + 10240 + r * 40 + c8 * 8);
            asm volatile("cp.async.cg.shared.global [%0], [%1], 16;\n" :: "r"(sa), "l"(g));
        }
        asm volatile("cp.async.commit_group;\n");
    };

    ldgA(0);
    cpB(0, smh);
    stsA(smh);
    asm volatile("cp.async.wait_group 0;\n");
    __syncthreads();

    for (int s = 0; s < 16; s++) {
        __half* cur = smh + (s & 1) * G1_STAGE_H;
        __half* nxt = smh + ((s + 1) & 1) * G1_STAGE_H;
        if (s + 1 < 16) { cpB((s + 1) * 32, nxt); ldgA((s + 1) * 32); }

        const __half* Ah = cur;
        const __half* Al = cur + 5120;
        const __half* Bh = cur + 10240;

        #pragma unroll
        for (int ks = 0; ks < 2; ks++) {
            int kb = ks * 16;
            uint32_t ah[2][4], al[2][4];
            #pragma unroll
            for (int mt = 0; mt < 2; mt++) {
                ldsm_x4(ah[mt], smem_u32(&Ah[(wm + mt * 16 + arow) * 40 + kb + acol]));
                ldsm_x4(al[mt], smem_u32(&Al[(wm + mt * 16 + arow) * 40 + kb + acol]));
            }
            uint32_t bh[8][2];
            #pragma unroll
            for (int g2 = 0; g2 < 4; g2++) {
                uint32_t tb[4];
                ldsm_x4(tb, smem_u32(&Bh[(wn + g2 * 16 + bn) * 40 + kb + bk]));
                bh[g2 * 2][0] = tb[0]; bh[g2 * 2][1] = tb[1];
                bh[g2 * 2 + 1][0] = tb[2]; bh[g2 * 2 + 1][1] = tb[3];
            }
            #pragma unroll
            for (int mt = 0; mt < 2; mt++)
                #pragma unroll
                for (int nt = 0; nt < 8; nt++) {
                    HMMA(acc[mt][nt], ah[mt], bh[nt]);
                    HMMA(acc[mt][nt], al[mt], bh[nt]);
                }
        }
        if (s + 1 < 16) { stsA(nxt); asm volatile("cp.async.wait_group 0;\n"); }
        __syncthreads();
    }

    #pragma unroll
    for (int mt = 0; mt < 2; mt++) {
        int row = rowBase + wm + mt * 16 + gid;
        #pragma unroll
        for (int nt = 0; nt < 8; nt++) {
            int col = wn + nt * 8 + tq * 2;
            if (row < NN)
                *(__half2*)&g_h1lin_s[(size_t)row * H1 + col] =
                    __floats2half2_rn(acc[mt][nt][0], acc[mt][nt][1]);
            if (row + 8 < NN)
                *(__half2*)&g_h1lin_s[(size_t)(row + 8) * H1 + col] =
                    __floats2half2_rn(acc[mt][nt][2], acc[mt][nt][3]);
        }
    }
}

// ---------------- scale h1lin in place by dinv[row] ----------------
__global__ void k_scale1() {
    int i = blockIdx.x * blockDim.x + threadIdx.x;   // uint4 id, NN*16 total
    if (i < NN * 16) {
        int row = i >> 4;
        float dd = g_dinv[row];
        uint4 v = ((uint4*)g_h1lin_s)[i];
        uint32_t* p = (uint32_t*)&v;
        #pragma unroll
        for (int q = 0; q < 4; q++) {
            float2 f = __half22float2(*(__half2*)&p[q]);
            __half2 o = __floats2half2_rn(f.x * dd, f.y * dd);
            p[q] = *(uint32_t*)&o;
        }
        ((uint4*)g_h1lin_s)[i] = v;
    }
}

// ---------------- GEMM2 fp16x1 HMMA: h2lin_s = dinv * (h1 @ W2h) ----------------
#define G2_STAGE_H 7680
#define G2_SMEM (2 * G2_STAGE_H * 2)

__global__ void __launch_bounds__(256, 1)
k_gemm2_mma() {
    extern __shared__ __half smh[];
    const int tid = threadIdx.x, lane = tid & 31, wid = tid >> 5;
    const int gid = lane >> 2, tq = lane & 3;
    const int rowBase = blockIdx.x * 128;
    const int wm = wid * 16;
    const int lt = lane >> 3, lr = lane & 7;
    const int arow = (lt & 1) * 8 + lr, acol = (lt >> 1) * 8;
    const int bn = (lt >> 1) * 8 + lr, bk = (lt & 1) * 8;

    float acc[8][4];
    #pragma unroll
    for (int nt = 0; nt < 8; nt++)
        #pragma unroll
        for (int i = 0; i < 4; i++) acc[nt][i] = 0.f;

    auto cpStage = [&](int kt, __half* buf) {
        #pragma unroll
        for (int l = 0; l < 2; l++) {
            int idx = tid + l * 256;
            int r = idx >> 2, c8 = idx & 3;
            int gr = rowBase + r;
            if (gr >= NN) gr = NN - 1;
            const __half* g = g_h1_h + (size_t)gr * H1 + kt + c8 * 8;
            uint32_t sa = smem_u32(buf + r * 40 + c8 * 8);
            asm volatile("cp.async.cg.shared.global [%0], [%1], 16;\n" :: "r"(sa), "l"(g));
        }
        {
            int idx = tid;
            int r = idx >> 2, c8 = idx & 3;
            const __half* g = g_w2h + (size_t)r * H1 + kt + c8 * 8;
            uint32_t sa = smem_u32(buf + 5120 + r * 40 + c8 * 8);
            asm volatile("cp.async.cg.shared.global [%0], [%1], 16;\n" :: "r"(sa), "l"(g));
        }
        asm volatile("cp.async.commit_group;\n");
    };

    cpStage(0, smh);
    asm volatile("cp.async.wait_group 0;\n");
    __syncthreads();

    for (int s = 0; s < 4; s++) {
        __half* cur = smh + (s & 1) * G2_STAGE_H;
        __half* nxt = smh + ((s + 1) & 1) * G2_STAGE_H;
        if (s + 1 < 4) cpStage((s + 1) * 32, nxt);

        const __half* Ah = cur;
        const __half* Bh = cur + 5120;

        #pragma unroll
        for (int ks = 0; ks < 2; ks++) {
            int kb = ks * 16;
            uint32_t a[4];
            ldsm_x4(a, smem_u32(&Ah[(wm + arow) * 40 + kb + acol]));
            uint32_t bh[8][2];
            #pragma unroll
            for (int g2 = 0; g2 < 4; g2++) {
                uint32_t tb[4];
                ldsm_x4(tb, smem_u32(&Bh[(g2 * 16 + bn) * 40 + kb + bk]));
                bh[g2 * 2][0] = tb[0]; bh[g2 * 2][1] = tb[1];
                bh[g2 * 2 + 1][0] = tb[2]; bh[g2 * 2 + 1][1] = tb[3];
            }
            #pragma unroll
            for (int nt = 0; nt < 8; nt++)
                HMMA(acc[nt], a, bh[nt]);
        }
        if (s + 1 < 4) asm volatile("cp.async.wait_group 0;\n");
        __syncthreads();
    }

    int row = rowBase + wm + gid;
    float dv0 = (row < NN) ? g_dinv[row] : 0.f;
    float dv1 = (row + 8 < NN) ? g_dinv[row + 8] : 0.f;
    #pragma unroll
    for (int nt = 0; nt < 8; nt++) {
        int col = nt * 8 + tq * 2;
        if (row < NN)
            *(__half2*)&g_h2lin_s[(size_t)row * H2 + col] =
                __floats2half2_rn(acc[nt][0] * dv0, acc[nt][1] * dv0);
        if (row + 8 < NN)
            *(__half2*)&g_h2lin_s[(size_t)(row + 8) * H2 + col] =
                __floats2half2_rn(acc[nt][2] * dv1, acc[nt][3] * dv1);
    }
}

// ---------------- aggregation: pure row-sum of pre-scaled fp16 rows ----------------
__global__ void k_agg128(const float* __restrict__ bias) {
    int gw = (blockIdx.x * blockDim.x + threadIdx.x) >> 5;
    int lane = threadIdx.x & 31;
    if (gw >= NN) return;
    int half = lane >> 4, fl = lane & 15;
    const uint4* H = (const uint4*)g_h1lin_s;
    float acc[8];
    #pragma unroll
    for (int i = 0; i < 8; i++) acc[i] = 0.f;
    if (half == 0) acc8_add(acc, H[(size_t)gw * 16 + fl]);
    int s0 = g_rowptr[gw], s1 = g_rowptr[gw + 1];
    for (int base = s0; base < s1; base += 32) {
        int rem = s1 - base;
        int cnt = rem < 32 ? rem : 32;
        int s = (lane < rem) ? g_csr[base + lane] : 0;
        int jj = 0;
        for (; jj + 4 <= cnt; jj += 4) {
            int ss0 = __shfl_sync(0xffffffffu, s, jj + half);
            int ss1 = __shfl_sync(0xffffffffu, s, jj + 2 + half);
            uint4 v0 = H[(size_t)ss0 * 16 + fl];
            uint4 v1 = H[(size_t)ss1 * 16 + fl];
            acc8_add(acc, v0);
            acc8_add(acc, v1);
        }
        for (; jj < cnt; jj += 2) {
            int j = jj + half;
            int ss = __shfl_sync(0xffffffffu, s, j < cnt ? j : 0);
            if (j < cnt) acc8_add(acc, H[(size_t)ss * 16 + fl]);
        }
    }
    #pragma unroll
    for (int i = 0; i < 8; i++) acc[i] += __shfl_xor_sync(0xffffffffu, acc[i], 16);
    if (half == 0) {
        float dd = g_dinv[gw];
        float4 b0 = *(const float4*)&bias[fl * 8];
        float4 b1 = *(const float4*)&bias[fl * 8 + 4];
        __half2 o[4];
        o[0] = __floats2half2_rn(fmaxf(acc[0] * dd + b0.x, 0.f), fmaxf(acc[1] * dd + b0.y, 0.f));
        o[1] = __floats2half2_rn(fmaxf(acc[2] * dd + b0.z, 0.f), fmaxf(acc[3] * dd + b0.w, 0.f));
        o[2] = __floats2half2_rn(fmaxf(acc[4] * dd + b1.x, 0.f), fmaxf(acc[5] * dd + b1.y, 0.f));
        o[3] = __floats2half2_rn(fmaxf(acc[6] * dd + b1.z, 0.f), fmaxf(acc[7] * dd + b1.w, 0.f));
        ((uint4*)g_h1_h)[(size_t)gw * 16 + fl] =
            make_uint4(*(uint32_t*)&o[0], *(uint32_t*)&o[1], *(uint32_t*)&o[2], *(uint32_t*)&o[3]);
    }
}

__global__ void k_agg64(const float* __restrict__ bias) {
    int gw = (blockIdx.x * blockDim.x + threadIdx.x) >> 5;
    int lane = threadIdx.x & 31;
    if (gw >= NN) return;
    int q4 = lane >> 3, fl = lane & 7;
    const uint4* H = (const uint4*)g_h2lin_s;
    float acc[8];
    #pragma unroll
    for (int i = 0; i < 8; i++) acc[i] = 0.f;
    if (q4 == 0) acc8_add(acc, H[(size_t)gw * 8 + fl]);
    int s0 = g_rowptr[gw], s1 = g_rowptr[gw + 1];
    for (int base = s0; base < s1; base += 32) {
        int rem = s1 - base;
        int cnt = rem < 32 ? rem : 32;
        int s = (lane < rem) ? g_csr[base + lane] : 0;
        int jj = 0;
        for (; jj + 8 <= cnt; jj += 8) {
            int ss0 = __shfl_sync(0xffffffffu, s, jj + q4);
            int ss1 = __shfl_sync(0xffffffffu, s, jj + 4 + q4);
            uint4 v0 = H[(size_t)ss0 * 8 + fl];
            uint4 v1 = H[(size_t)ss1 * 8 + fl];
            acc8_add(acc, v0);
            acc8_add(acc, v1);
        }
        for (; jj < cnt; jj += 4) {
            int j = jj + q4;
            int ss = __shfl_sync(0xffffffffu, s, j < cnt ? j : 0);
            if (j < cnt) acc8_add(acc, H[(size_t)ss * 8 + fl]);
        }
    }
    #pragma unroll
    for (int i = 0; i < 8; i++) {
        acc[i] += __shfl_xor_sync(0xffffffffu, acc[i], 8);
        acc[i] += __shfl_xor_sync(0xffffffffu, acc[i], 16);
    }
    if (lane < 8) {
        float dd = g_dinv[gw];
        float4 b0 = *(const float4*)&bias[fl * 8];
        float4 b1 = *(const float4*)&bias[fl * 8 + 4];
        __half2 o[4];
        o[0] = __floats2half2_rn(fmaxf(acc[0] * dd + b0.x, 0.f), fmaxf(acc[1] * dd + b0.y, 0.f));
        o[1] = __floats2half2_rn(fmaxf(acc[2] * dd + b0.z, 0.f), fmaxf(acc[3] * dd + b0.w, 0.f));
        o[2] = __floats2half2_rn(fmaxf(acc[4] * dd + b1.x, 0.f), fmaxf(acc[5] * dd + b1.y, 0.f));
        o[3] = __floats2half2_rn(fmaxf(acc[6] * dd + b1.z, 0.f), fmaxf(acc[7] * dd + b1.w, 0.f));
        ((uint4*)g_h2_h)[(size_t)gw * 8 + fl] =
            make_uint4(*(uint32_t*)&o[0], *(uint32_t*)&o[1], *(uint32_t*)&o[2], *(uint32_t*)&o[3]);
    }
}

// ---------------- edge scorer fp16x1 HMMA, 256 edges/block ----------------
// halves: Th@0 (256*72=18432) Wh@18432 (4608) -> 23040 halves = 46080 B
// floats after: w2s@46080 (128 f), b1s@46592 (64 f) -> total 46848 B
#define SC_SMEM 46848

__global__ void __launch_bounds__(256)
k_score_mma(const int* __restrict__ la, const int* __restrict__ lb,
            const float* __restrict__ fcb1,
            const float* __restrict__ fcW2, const float* __restrict__ fcb2,
            float* __restrict__ out) {
    extern __shared__ __half smh[];
    __half* Th = smh;
    __half* Wh = smh + 18432;
    float* w2s = (float*)((char*)smh + 46080);
    float* b1s = (float*)((char*)smh + 46592);
    const int tid = threadIdx.x, lane = tid & 31, wid = tid >> 5;
    const int gid = lane >> 2, tq = lane & 3;
    const int e0 = blockIdx.x * 256;
    const int lt = lane >> 3, lr = lane & 7;
    const int arow = (lt & 1) * 8 + lr, acol = (lt >> 1) * 8;
    const int bn = (lt >> 1) * 8 + lr, bk = (lt & 1) * 8;

    #pragma unroll
    for (int l = 0; l < 2; l++) {
        int j = tid + l * 256;               // 512 chunks: 64 rows x 8
        int n = j >> 3, c8 = j & 7;
        const __half* g = g_fw1h + (size_t)n * 64 + c8 * 8;
        uint32_t sa = smem_u32(Wh + n * 72 + c8 * 8);
        asm volatile("cp.async.cg.shared.global [%0], [%1], 16;\n" :: "r"(sa), "l"(g));
    }
    asm volatile("cp.async.commit_group;\n");
    if (tid < 128) w2s[tid] = fcW2[tid];
    if (tid < 64)  b1s[tid] = fcb1[tid];

    #pragma unroll
    for (int l = 0; l < 8; l++) {
        int idx = tid + l * 256;             // 2048 = 256 edges x 8 chunks
        int e = idx >> 3, c8 = idx & 7;
        int eg = e0 + e;
        if (eg >= NL) eg = NL - 1;
        int a = la[eg], b = lb[eg];
        uint4 va = *(const uint4*)&g_h2_h[(size_t)a * H2 + c8 * 8];
        uint4 vb = *(const uint4*)&g_h2_h[(size_t)b * H2 + c8 * 8];
        uint32_t th[4];
        const uint32_t* pa = (const uint32_t*)&va;
        const uint32_t* pb = (const uint32_t*)&vb;
        #pragma unroll
        for (int q = 0; q < 4; q++) {
            float2 fa = __half22float2(*(__half2*)&pa[q]);
            float2 fb = __half22float2(*(__half2*)&pb[q]);
            __half2 hh = __floats2half2_rn(fa.x * fb.x, fa.y * fb.y);
            th[q] = *(uint32_t*)&hh;
        }
        *(uint4*)&Th[e * 72 + c8 * 8] = make_uint4(th[0], th[1], th[2], th[3]);
    }
    asm volatile("cp.async.wait_group 0;\n");
    __syncthreads();

    float acc[2][8][4];
    #pragma unroll
    for (int mt = 0; mt < 2; mt++)
        #pragma unroll
        for (int nt = 0; nt < 8; nt++)
            #pragma unroll
            for (int i = 0; i < 4; i++) acc[mt][nt][i] = 0.f;

    const int rowT = wid * 32;
    #pragma unroll
    for (int ks = 0; ks < 4; ks++) {
        int kb = ks * 16;
        uint32_t ah[2][4];
        #pragma unroll
        for (int mt = 0; mt < 2; mt++)
            ldsm_x4(ah[mt], smem_u32(&Th[(rowT + mt * 16 + arow) * 72 + kb + acol]));
        uint32_t bh[8][2];
        #pragma unroll
        for (int g2 = 0; g2 < 4; g2++) {
            uint32_t tb[4];
            ldsm_x4(tb, smem_u32(&Wh[(g2 * 16 + bn) * 72 + kb + bk]));
            bh[g2 * 2][0] = tb[0]; bh[g2 * 2][1] = tb[1];
            bh[g2 * 2 + 1][0] = tb[2]; bh[g2 * 2 + 1][1] = tb[3];
        }
        #pragma unroll
        for (int mt = 0; mt < 2; mt++)
            #pragma unroll
            for (int nt = 0; nt < 8; nt++)
                HMMA(acc[mt][nt], ah[mt], bh[nt]);
    }

    // second tiny layer in registers
    #pragma unroll
    for (int mt = 0; mt < 2; mt++) {
        float p00 = 0.f, p01 = 0.f, p10 = 0.f, p11 = 0.f;
        #pragma unroll
        for (int nt = 0; nt < 8; nt++) {
            int col = nt * 8 + tq * 2;
            float4 w2a = *(float4*)&w2s[col * 2];
            float b0v = b1s[col], b1v = b1s[col + 1];
            float u0 = fmaxf(acc[mt][nt][0] + b0v, 0.f);
            float u1 = fmaxf(acc[mt][nt][1] + b1v, 0.f);
            float u2 = fmaxf(acc[mt][nt][2] + b0v, 0.f);
            float u3 = fmaxf(acc[mt][nt][3] + b1v, 0.f);
            p00 += u0 * w2a.x + u1 * w2a.z;
            p01 += u0 * w2a.y + u1 * w2a.w;
            p10 += u2 * w2a.x + u3 * w2a.z;
            p11 += u2 * w2a.y + u3 * w2a.w;
        }
        #pragma unroll
        for (int off = 1; off <= 2; off <<= 1) {
            p00 += __shfl_xor_sync(0xffffffffu, p00, off);
            p01 += __shfl_xor_sync(0xffffffffu, p01, off);
            p10 += __shfl_xor_sync(0xffffffffu, p10, off);
            p11 += __shfl_xor_sync(0xffffffffu, p11, off);
        }
        if (tq == 0) {
            float c0 = fcb2[0], c1 = fcb2[1];
            int e = e0 + rowT + mt * 16 + gid;
            if (e < NL)     *(float2*)&out[(size_t)e * 2]       = make_float2(p00 + c0, p01 + c1);
            if (e + 8 < NL) *(float2*)&out[(size_t)(e + 8) * 2] = make_float2(p10 + c0, p11 + c1);
        }
    }
}

// ---------------- launch ----------------
extern "C" void kernel_launch(void* const* d_in, const int* in_sizes, int n_in,
                              void* d_out, int out_size) {
    const float* x    = (const float*)d_in[0];
    const float* W1   = (const float*)d_in[1];
    const float* b1   = (const float*)d_in[2];
    const float* W2   = (const float*)d_in[3];
    const float* b2   = (const float*)d_in[4];
    const float* fcW1 = (const float*)d_in[5];
    const float* fcb1 = (const float*)d_in[6];
    const float* fcW2 = (const float*)d_in[7];
    const float* fcb2 = (const float*)d_in[8];
    const int* eidx = (const int*)d_in[9];
    const int* elab = (const int*)d_in[10];
    const int* src = eidx;
    const int* dst = eidx + NE;
    const int* la = elab;
    const int* lb = elab + NL;
    float* out = (float*)d_out;

    static int attr_done = 0;
    static cudaStream_t s2;
    static cudaEvent_t evA, evB, evC;
    static void* p_count = nullptr;
    if (!attr_done) {
        cudaFuncSetAttribute(k_gemm1_mma, cudaFuncAttributeMaxDynamicSharedMemorySize, G1_SMEM);
        cudaFuncSetAttribute(k_gemm2_mma, cudaFuncAttributeMaxDynamicSharedMemorySize, G2_SMEM);
        cudaFuncSetAttribute(k_score_mma, cudaFuncAttributeMaxDynamicSharedMemorySize, SC_SMEM);
        cudaStreamCreateWithFlags(&s2, cudaStreamNonBlocking);
        cudaEventCreateWithFlags(&evA, cudaEventDisableTiming);
        cudaEventCreateWithFlags(&evB, cudaEventDisableTiming);
        cudaEventCreateWithFlags(&evC, cudaEventDisableTiming);
        cudaGetSymbolAddress(&p_count, g_count);
        attr_done = 1;
    }

    // full fork: entire CSR chain on s2, weight prep + gemm1 on default
    cudaEventRecord(evA, 0);
    cudaStreamWaitEvent(s2, evA, 0);

    cudaMemsetAsync(p_count, 0, NN * sizeof(int), s2);
    k_hist<<<(NE + 255) / 256, 256, 0, s2>>>(dst);
    k_bsum<<<NBLK, 1024, 0, s2>>>();          // also computes dinv
    cudaEventRecord(evC, s2);                 // dinv ready
    k_scat<<<NBLK, 1024, 0, s2>>>();          // self-contained prefix (no bscan)
    k_fill<<<(NE + 255) / 256, 256, 0, s2>>>(src, dst);
    cudaEventRecord(evB, s2);                 // csr ready

    k_wprep<<<(WP_N + 255) / 256, 256>>>(W1, W2, fcW1);
    k_gemm1_mma<<<(NN + 127) / 128, 256, G1_SMEM>>>(x);

    // scale1 needs only dinv + gemm1 — overlap with scat/fill
    cudaStreamWaitEvent(0, evC, 0);
    k_scale1<<<(NN * 16 + 255) / 256, 256>>>();

    // full join for the gather
    cudaStreamWaitEvent(0, evB, 0);
    k_agg128<<<(NN * 32 + 255) / 256, 256>>>(b1);
    k_gemm2_mma<<<(NN + 127) / 128, 256, G2_SMEM>>>();
    k_agg64<<<(NN * 32 + 255) / 256, 256>>>(b2);
    k_score_mma<<<(NL + 255) / 256, 256, SC_SMEM>>>(la, lb, fcb1, fcW2, fcb2, out);
}